// round 2
// baseline (speedup 1.0000x reference)
#include <cuda_runtime.h>
#include <math.h>

// Problem constants
#define T_      8
#define N_      64
#define HW_     256
#define HID_    128
#define NA_     128
#define HX_     514     // 1 + 128 + 1 + 128 + 256
#define PASS_   258     // passthrough columns
#define ROWS_   512     // T*N
#define OUT1_   263168  // 512*514
#define OUT2_   32896   // 64*514
#define OUTT_   296064

typedef unsigned long long ull;

// ------------------------- scratch (device globals; no allocs) -------------
__device__ float g_gi[HW_ * 384];            // 256x384
__device__ float g_K[HW_ * HID_];            // 256x128
__device__ float g_Y1[HW_ * NA_ * HID_];     // rows=(w*128+a), 128 cols
__device__ float g_Y2[HW_ * NA_ * HID_];
__device__ float g_P[HW_ * HW_ * NA_];       // P[w][s][a]  33.5MB
__device__ float g_R[ROWS_ * HW_];           // rewards [row][w]
__device__ float g_V[2][ROWS_ * HW_];        // ping-pong values

// ------------------------- f32x2 helpers -----------------------------------
__device__ __forceinline__ void fma2(ull& d, ull a, ull b) {
    asm("fma.rn.f32x2 %0, %1, %2, %0;" : "+l"(d) : "l"(a), "l"(b));
}
__device__ __forceinline__ float2 unpack2(ull u) {
    float2 f;
    asm("mov.b64 {%0, %1}, %2;" : "=f"(f.x), "=f"(f.y) : "l"(u));
    return f;
}

// ------------------------- shared GEMM tile core ----------------------------
// Xs2: [32][64] float2, entry = {x,x} duplicated (A-operand rows)
// Bs : [32][128] float (B-operand cols)
// acc[r][c] accumulates rows ty*8+r, col-pair (tx*8+2c, tx*8+2c+1)
__device__ __forceinline__ void tile_fma(const float2 (&Xs2)[32][64],
                                         const float (&Bs)[32][128],
                                         ull (&acc)[8][4], int tx, int ty) {
    const ull* Xu = reinterpret_cast<const ull*>(&Xs2[0][0]);
#pragma unroll 8
    for (int k = 0; k < 32; ++k) {
        ulonglong2 a0 = *reinterpret_cast<const ulonglong2*>(Xu + k * 64 + ty * 8 + 0);
        ulonglong2 a1 = *reinterpret_cast<const ulonglong2*>(Xu + k * 64 + ty * 8 + 2);
        ulonglong2 a2 = *reinterpret_cast<const ulonglong2*>(Xu + k * 64 + ty * 8 + 4);
        ulonglong2 a3 = *reinterpret_cast<const ulonglong2*>(Xu + k * 64 + ty * 8 + 6);
        const ull* Bp = reinterpret_cast<const ull*>(&Bs[k][tx * 8]);
        ulonglong2 b0 = *reinterpret_cast<const ulonglong2*>(Bp + 0);
        ulonglong2 b1 = *reinterpret_cast<const ulonglong2*>(Bp + 2);
        ull av[8] = {a0.x, a0.y, a1.x, a1.y, a2.x, a2.y, a3.x, a3.y};
        ull bv[4] = {b0.x, b0.y, b1.x, b1.y};
#pragma unroll
        for (int r = 0; r < 8; ++r)
#pragma unroll
            for (int c = 0; c < 4; ++c) fma2(acc[r][c], av[r], bv[c]);
    }
}

// ------------------------- K1: gi = S @ w_ih^T + b_ih ----------------------
__global__ void gi_kernel(const float* __restrict__ S, const float* __restrict__ w_ih,
                          const float* __restrict__ b_ih) {
    __shared__ float Ss[HID_];
    int blk = blockIdx.x;           // s row (0..255)
    int o = threadIdx.x;            // 0..383
    if (o < HID_) Ss[o] = S[blk * HID_ + o];
    __syncthreads();
    float acc = b_ih[o];
#pragma unroll 8
    for (int k = 0; k < HID_; k += 4) {
        float4 w = *reinterpret_cast<const float4*>(&w_ih[o * HID_ + k]);
        acc += Ss[k] * w.x + Ss[k + 1] * w.y + Ss[k + 2] * w.z + Ss[k + 3] * w.w;
    }
    g_gi[blk * 384 + o] = acc;
}

// ------------------------- K2: GRU scan (single block) ---------------------
// dyn smem: whhT[128][384] | h[128] | gh[384]
__global__ void gru_kernel(const float* __restrict__ w_hh, const float* __restrict__ b_hh) {
    extern __shared__ float sm[];
    float* whhT = sm;                 // [k][o] : k*384 + o
    float* hs = sm + 49152;           // [128]
    float* ghs = hs + 128;            // [384]
    int tid = threadIdx.x;            // 0..383

    // load transposed weights: whhT[k*384+o] = w_hh[o*128+k]
    for (int idx = tid; idx < 49152; idx += 384) {
        int o = idx % 384, k = idx / 384;
        whhT[k * 384 + o] = w_hh[o * HID_ + k];
    }
    if (tid < HID_) hs[tid] = 0.0f;
    float bh = b_hh[tid];
    __syncthreads();

    for (int t = 0; t < HW_; ++t) {
        float acc = bh;
#pragma unroll 8
        for (int k = 0; k < HID_; k += 4) {
            float4 h4 = *reinterpret_cast<const float4*>(&hs[k]);
            acc = fmaf(h4.x, whhT[(k + 0) * 384 + tid], acc);
            acc = fmaf(h4.y, whhT[(k + 1) * 384 + tid], acc);
            acc = fmaf(h4.z, whhT[(k + 2) * 384 + tid], acc);
            acc = fmaf(h4.w, whhT[(k + 3) * 384 + tid], acc);
        }
        ghs[tid] = acc;
        __syncthreads();
        if (tid < HID_) {
            int j = tid;
            float gir = g_gi[t * 384 + j];
            float giz = g_gi[t * 384 + 128 + j];
            float gin = g_gi[t * 384 + 256 + j];
            float r = 1.0f / (1.0f + expf(-(gir + ghs[j])));
            float z = 1.0f / (1.0f + expf(-(giz + ghs[j + 128])));
            float n = tanhf(gin + r * ghs[j + 256]);
            float hn = (1.0f - z) * n + z * hs[j];
            hs[j] = hn;
            g_K[t * HID_ + j] = hn;
        }
        __syncthreads();
    }
}

// ------------------------- K3: MLP layer 1 ---------------------------------
// rows = w*128 + a ; out Y1[row][j] = relu((A[a]+S[w]) . W1[j] + b1[j])
__global__ __launch_bounds__(128) void mlp1_kernel(const float* __restrict__ A,
                                                   const float* __restrict__ S,
                                                   const float* __restrict__ W1,
                                                   const float* __restrict__ b1) {
    __shared__ float2 Xs2[32][64];
    __shared__ float Bs[32][128];
    int rb = blockIdx.x * 64;
    int w = rb >> 7, a0 = rb & 127;
    int tid = threadIdx.x, tx = tid & 15, ty = tid >> 4;
    ull acc[8][4] = {};

    for (int kc = 0; kc < HID_; kc += 32) {
        __syncthreads();
#pragma unroll
        for (int j = 0; j < 4; ++j) {  // X stage: 512 float4
            int lin = tid + j * 128;
            int r = lin & 63, kq = lin >> 6;
            float4 av = *reinterpret_cast<const float4*>(&A[(a0 + r) * HID_ + kc + kq * 4]);
            float4 sv = *reinterpret_cast<const float4*>(&S[w * HID_ + kc + kq * 4]);
            float v0 = av.x + sv.x, v1 = av.y + sv.y, v2 = av.z + sv.z, v3 = av.w + sv.w;
            Xs2[kq * 4 + 0][r] = make_float2(v0, v0);
            Xs2[kq * 4 + 1][r] = make_float2(v1, v1);
            Xs2[kq * 4 + 2][r] = make_float2(v2, v2);
            Xs2[kq * 4 + 3][r] = make_float2(v3, v3);
        }
#pragma unroll
        for (int j = 0; j < 8; ++j) {  // B stage (transpose W1)
            float4 wv = *reinterpret_cast<const float4*>(&W1[tid * HID_ + kc + j * 4]);
            Bs[j * 4 + 0][tid] = wv.x;
            Bs[j * 4 + 1][tid] = wv.y;
            Bs[j * 4 + 2][tid] = wv.z;
            Bs[j * 4 + 3][tid] = wv.w;
        }
        __syncthreads();
        tile_fma(Xs2, Bs, acc, tx, ty);
    }
    float bb[8];
#pragma unroll
    for (int c = 0; c < 8; ++c) bb[c] = b1[tx * 8 + c];
#pragma unroll
    for (int i = 0; i < 8; ++i) {
        float o[8];
#pragma unroll
        for (int c = 0; c < 4; ++c) {
            float2 f = unpack2(acc[i][c]);
            o[2 * c] = fmaxf(f.x + bb[2 * c], 0.0f);
            o[2 * c + 1] = fmaxf(f.y + bb[2 * c + 1], 0.0f);
        }
        float* dst = &g_Y1[(rb + ty * 8 + i) * HID_ + tx * 8];
        *reinterpret_cast<float4*>(dst) = make_float4(o[0], o[1], o[2], o[3]);
        *reinterpret_cast<float4*>(dst + 4) = make_float4(o[4], o[5], o[6], o[7]);
    }
}

// ------------------------- K4: MLP layer 2 ---------------------------------
__global__ __launch_bounds__(128) void mlp2_kernel(const float* __restrict__ W2,
                                                   const float* __restrict__ b2) {
    __shared__ float2 Xs2[32][64];
    __shared__ float Bs[32][128];
    int rb = blockIdx.x * 64;
    int tid = threadIdx.x, tx = tid & 15, ty = tid >> 4;
    ull acc[8][4] = {};

    for (int kc = 0; kc < HID_; kc += 32) {
        __syncthreads();
#pragma unroll
        for (int j = 0; j < 4; ++j) {
            int lin = tid + j * 128;
            int r = lin & 63, kq = lin >> 6;
            float4 v = *reinterpret_cast<const float4*>(&g_Y1[(rb + r) * HID_ + kc + kq * 4]);
            Xs2[kq * 4 + 0][r] = make_float2(v.x, v.x);
            Xs2[kq * 4 + 1][r] = make_float2(v.y, v.y);
            Xs2[kq * 4 + 2][r] = make_float2(v.z, v.z);
            Xs2[kq * 4 + 3][r] = make_float2(v.w, v.w);
        }
#pragma unroll
        for (int j = 0; j < 8; ++j) {
            float4 wv = *reinterpret_cast<const float4*>(&W2[tid * HID_ + kc + j * 4]);
            Bs[j * 4 + 0][tid] = wv.x;
            Bs[j * 4 + 1][tid] = wv.y;
            Bs[j * 4 + 2][tid] = wv.z;
            Bs[j * 4 + 3][tid] = wv.w;
        }
        __syncthreads();
        tile_fma(Xs2, Bs, acc, tx, ty);
    }
    float bb[8];
#pragma unroll
    for (int c = 0; c < 8; ++c) bb[c] = b2[tx * 8 + c];
#pragma unroll
    for (int i = 0; i < 8; ++i) {
        float o[8];
#pragma unroll
        for (int c = 0; c < 4; ++c) {
            float2 f = unpack2(acc[i][c]);
            o[2 * c] = fmaxf(f.x + bb[2 * c], 0.0f);
            o[2 * c + 1] = fmaxf(f.y + bb[2 * c + 1], 0.0f);
        }
        float* dst = &g_Y2[(rb + ty * 8 + i) * HID_ + tx * 8];
        *reinterpret_cast<float4*>(dst) = make_float4(o[0], o[1], o[2], o[3]);
        *reinterpret_cast<float4*>(dst + 4) = make_float4(o[4], o[5], o[6], o[7]);
    }
}

// ------------------------- K5: logits L[w,s,a] = K[s,:] . Y2[(w,a),:] ------
__global__ __launch_bounds__(128) void logits_kernel() {
    __shared__ float2 Xs2[32][64];
    __shared__ float Bs[32][128];
    int s0 = blockIdx.x * 64;  // 4 tiles
    int w = blockIdx.y;
    int tid = threadIdx.x, tx = tid & 15, ty = tid >> 4;
    ull acc[8][4] = {};

    for (int kc = 0; kc < HID_; kc += 32) {
        __syncthreads();
#pragma unroll
        for (int j = 0; j < 4; ++j) {
            int lin = tid + j * 128;
            int r = lin & 63, kq = lin >> 6;
            float4 v = *reinterpret_cast<const float4*>(&g_K[(s0 + r) * HID_ + kc + kq * 4]);
            Xs2[kq * 4 + 0][r] = make_float2(v.x, v.x);
            Xs2[kq * 4 + 1][r] = make_float2(v.y, v.y);
            Xs2[kq * 4 + 2][r] = make_float2(v.z, v.z);
            Xs2[kq * 4 + 3][r] = make_float2(v.w, v.w);
        }
#pragma unroll
        for (int j = 0; j < 8; ++j) {  // B stage: Y2 row (w*128 + a=tid)
            float4 wv = *reinterpret_cast<const float4*>(
                &g_Y2[(w * NA_ + tid) * HID_ + kc + j * 4]);
            Bs[j * 4 + 0][tid] = wv.x;
            Bs[j * 4 + 1][tid] = wv.y;
            Bs[j * 4 + 2][tid] = wv.z;
            Bs[j * 4 + 3][tid] = wv.w;
        }
        __syncthreads();
        tile_fma(Xs2, Bs, acc, tx, ty);
    }
#pragma unroll
    for (int i = 0; i < 8; ++i) {
        float o[8];
#pragma unroll
        for (int c = 0; c < 4; ++c) {
            float2 f = unpack2(acc[i][c]);
            o[2 * c] = f.x;
            o[2 * c + 1] = f.y;
        }
        float* dst = &g_P[((size_t)w * HW_ + s0 + ty * 8 + i) * NA_ + tx * 8];
        *reinterpret_cast<float4*>(dst) = make_float4(o[0], o[1], o[2], o[3]);
        *reinterpret_cast<float4*>(dst + 4) = make_float4(o[4], o[5], o[6], o[7]);
    }
}

// ------------------------- K6: softmax over s (in place) -------------------
__global__ void softmax_kernel() {
    int w = blockIdx.x, a = threadIdx.x;  // 128 threads
    float* base = g_P + (size_t)w * HW_ * NA_ + a;
    float m = -1e30f;
#pragma unroll 8
    for (int s = 0; s < HW_; ++s) m = fmaxf(m, base[s * NA_]);
    float sum = 0.0f;
#pragma unroll 8
    for (int s = 0; s < HW_; ++s) {
        float e = expf(base[s * NA_] - m);
        base[s * NA_] = e;
        sum += e;
    }
    float inv = 1.0f / sum;
#pragma unroll 8
    for (int s = 0; s < HW_; ++s) base[s * NA_] *= inv;
}

// ------------------------- K7: rewards + V0 init ---------------------------
__global__ void init_kernel(const float* __restrict__ inputs) {
    int idx = blockIdx.x * blockDim.x + threadIdx.x;  // 512*256
    int row = idx >> 8, s = idx & 255;
    float v = inputs[row * 257 + s];
    g_R[idx] = v;
    g_V[0][idx] = v;  // first bellman iteration from V=0 yields rewards
}

// ------------------------- K8: Bellman iteration ---------------------------
// Vdst[row][w] = R[row][w] + max_a sum_s Vsrc[row][s] * P[w][s][a]
__global__ __launch_bounds__(128) void bellman_kernel(int srcIdx) {
    __shared__ float2 Xs2[32][64];
    __shared__ float Bs[32][128];
    const float* src = g_V[srcIdx];
    float* dst = g_V[srcIdx ^ 1];
    int rb = blockIdx.x * 64;
    int w = blockIdx.y;
    int tid = threadIdx.x, tx = tid & 15, ty = tid >> 4;
    ull acc[8][4] = {};

    for (int kc = 0; kc < HW_; kc += 32) {
        __syncthreads();
#pragma unroll
        for (int j = 0; j < 4; ++j) {  // stage V rows (duplicated pairs)
            int lin = tid + j * 128;
            int r = lin & 63, kq = lin >> 6;
            float4 v = *reinterpret_cast<const float4*>(&src[(rb + r) * HW_ + kc + kq * 4]);
            Xs2[kq * 4 + 0][r] = make_float2(v.x, v.x);
            Xs2[kq * 4 + 1][r] = make_float2(v.y, v.y);
            Xs2[kq * 4 + 2][r] = make_float2(v.z, v.z);
            Xs2[kq * 4 + 3][r] = make_float2(v.w, v.w);
        }
#pragma unroll
        for (int j = 0; j < 8; ++j) {  // stage P[w][kc+k][:] directly
            int lin = tid + j * 128;
            int a4 = lin & 31, k = lin >> 5;
            float4 p = *reinterpret_cast<const float4*>(
                &g_P[((size_t)w * HW_ + kc + k) * NA_ + a4 * 4]);
            *reinterpret_cast<float4*>(&Bs[k][a4 * 4]) = p;
        }
        __syncthreads();
        tile_fma(Xs2, Bs, acc, tx, ty);
    }
    __syncthreads();
    float* red = reinterpret_cast<float*>(&Xs2[0][0]);  // 64*16 floats
#pragma unroll
    for (int i = 0; i < 8; ++i) {
        float m = -1e30f;
#pragma unroll
        for (int c = 0; c < 4; ++c) {
            float2 f = unpack2(acc[i][c]);
            m = fmaxf(m, fmaxf(f.x, f.y));
        }
        red[(ty * 8 + i) * 16 + tx] = m;
    }
    __syncthreads();
    if (tid < 64) {
        float m = -1e30f;
#pragma unroll
        for (int g = 0; g < 16; ++g) m = fmaxf(m, red[tid * 16 + g]);
        dst[(rb + tid) * HW_ + w] = g_R[(rb + tid) * HW_ + w] + m;
    }
}

// ------------------------- K9: output assembly -----------------------------
__global__ void assemble_kernel(const float* __restrict__ rnn_hxs, float* __restrict__ out,
                                int out_size) {
    int idx = blockIdx.x * blockDim.x + threadIdx.x;
    if (idx >= out_size || idx >= OUTT_) return;
    int row, c;
    if (idx < OUT1_) {
        row = idx / HX_;
        c = idx - row * HX_;
    } else {
        int k = idx - OUT1_;
        int r2 = k / HX_;
        c = k - r2 * HX_;
        row = 448 + r2;  // t = 7 slice
    }
    float v = (c < PASS_) ? rnn_hxs[row * HX_ + c] : g_V[1][row * HW_ + (c - PASS_)];
    out[idx] = v;
}

// ------------------------- launcher ----------------------------------------
extern "C" void kernel_launch(void* const* d_in, const int* in_sizes, int n_in,
                              void* d_out, int out_size) {
    const float* inputs = (const float*)d_in[0];   // (8,64,257)
    const float* rnn_hxs = (const float*)d_in[1];  // (8,64,514)
    const float* S = (const float*)d_in[2];        // (256,128)
    const float* A = (const float*)d_in[3];        // (128,128)
    const float* w_ih = (const float*)d_in[4];     // (384,128)
    const float* w_hh = (const float*)d_in[5];     // (384,128)
    const float* b_ih = (const float*)d_in[6];     // (384,)
    const float* b_hh = (const float*)d_in[7];     // (384,)
    const float* W1 = (const float*)d_in[8];       // (128,128)
    const float* b1 = (const float*)d_in[9];       // (128,)
    const float* W2 = (const float*)d_in[10];      // (128,128)
    const float* b2 = (const float*)d_in[11];      // (128,)
    float* out = (float*)d_out;

    const int GRU_SMEM = (49152 + 128 + 384) * 4;  // 198656 B
    cudaFuncSetAttribute(gru_kernel, cudaFuncAttributeMaxDynamicSharedMemorySize, GRU_SMEM);

    gi_kernel<<<HW_, 384>>>(S, w_ih, b_ih);
    gru_kernel<<<1, 384, GRU_SMEM>>>(w_hh, b_hh);
    mlp1_kernel<<<HW_ * NA_ / 64, 128>>>(A, S, W1, b1);
    mlp2_kernel<<<HW_ * NA_ / 64, 128>>>(W2, b2);
    logits_kernel<<<dim3(4, HW_), 128>>>();
    softmax_kernel<<<HW_, 128>>>();
    init_kernel<<<ROWS_, 256>>>(inputs);
    for (int it = 0; it < 15; ++it) {
        bellman_kernel<<<dim3(8, HW_), 128>>>(it & 1);
    }
    int total = out_size < OUTT_ ? out_size : OUTT_;
    assemble_kernel<<<(total + 255) / 256, 256>>>(rnn_hxs, out, out_size);
}

// round 4
// speedup vs baseline: 2.5847x; 2.5847x over previous
#include <cuda_runtime.h>
#include <cuda_bf16.h>
#include <math.h>
#include <stdint.h>

// Problem constants
#define T_      8
#define N_      64
#define HW_     256
#define HID_    128
#define NA_     128
#define HX_     514
#define PASS_   258
#define ROWS_   512
#define OUT1_   263168
#define OUTT_   296064

typedef unsigned long long ull;

// ------------------------- scratch (device globals; no allocs) -------------
__device__ float g_gi[HW_ * 384];
__device__ float g_K[HW_ * HID_];
__device__ float g_Y1[HW_ * NA_ * HID_];
__device__ float g_Y2[HW_ * NA_ * HID_];
__device__ float g_P[HW_ * HW_ * NA_];                    // P[w][s][a] fp32
__device__ __nv_bfloat16 g_Pth[(size_t)HW_ * NA_ * HW_];  // [w][a][s] hi
__device__ __nv_bfloat16 g_Ptl[(size_t)HW_ * NA_ * HW_];  // [w][a][s] lo
__device__ float g_R[ROWS_ * HW_];
__device__ float g_V[ROWS_ * HW_];                        // fp32 (final)
__device__ __nv_bfloat16 g_Vh[2][ROWS_ * HW_];
__device__ __nv_bfloat16 g_Vl[2][ROWS_ * HW_];

// ------------------------- ptx helpers -------------------------------------
__device__ __forceinline__ void fma2(ull& d, ull a, ull b) {
    asm("fma.rn.f32x2 %0, %1, %2, %0;" : "+l"(d) : "l"(a), "l"(b));
}
__device__ __forceinline__ float2 unpack2(ull u) {
    float2 f;
    asm("mov.b64 {%0, %1}, %2;" : "=f"(f.x), "=f"(f.y) : "l"(u));
    return f;
}
__device__ __forceinline__ ull pack2(float x, float y) {
    ull u;
    asm("mov.b64 %0, {%1, %2};" : "=l"(u) : "f"(x), "f"(y));
    return u;
}
__device__ __forceinline__ uint32_t smem_u32(const void* p) {
    uint32_t a;
    asm("{ .reg .u64 t; cvta.to.shared.u64 t, %1; cvt.u32.u64 %0, t; }" : "=r"(a) : "l"(p));
    return a;
}
__device__ __forceinline__ void cp_async16(uint32_t dst, const void* src) {
    asm volatile("cp.async.cg.shared.global [%0], [%1], 16;" ::"r"(dst), "l"(src) : "memory");
}
#define CP_COMMIT() asm volatile("cp.async.commit_group;" ::: "memory")

__device__ __forceinline__ void ldsm_x4(uint32_t* r, uint32_t addr) {
    asm volatile("ldmatrix.sync.aligned.m8n8.x4.shared.b16 {%0,%1,%2,%3}, [%4];"
                 : "=r"(r[0]), "=r"(r[1]), "=r"(r[2]), "=r"(r[3]) : "r"(addr));
}
__device__ __forceinline__ void mma16816(float* c, const uint32_t* a, const uint32_t* b) {
    asm volatile(
        "mma.sync.aligned.m16n8k16.row.col.f32.bf16.bf16.f32 "
        "{%0,%1,%2,%3}, {%4,%5,%6,%7}, {%8,%9}, {%0,%1,%2,%3};"
        : "+f"(c[0]), "+f"(c[1]), "+f"(c[2]), "+f"(c[3])
        : "r"(a[0]), "r"(a[1]), "r"(a[2]), "r"(a[3]), "r"(b[0]), "r"(b[1]));
}

// ------------------------- f32x2 tile core (mlp/logits) --------------------
__device__ __forceinline__ void tile_fma(const float2 (&Xs2)[32][64], const float (&Bs)[32][128],
                                         ull (&acc)[8][4], int tx, int ty) {
    const ull* Xu = reinterpret_cast<const ull*>(&Xs2[0][0]);
#pragma unroll 8
    for (int k = 0; k < 32; ++k) {
        ulonglong2 a0 = *reinterpret_cast<const ulonglong2*>(Xu + k * 64 + ty * 8 + 0);
        ulonglong2 a1 = *reinterpret_cast<const ulonglong2*>(Xu + k * 64 + ty * 8 + 2);
        ulonglong2 a2 = *reinterpret_cast<const ulonglong2*>(Xu + k * 64 + ty * 8 + 4);
        ulonglong2 a3 = *reinterpret_cast<const ulonglong2*>(Xu + k * 64 + ty * 8 + 6);
        const ull* Bp = reinterpret_cast<const ull*>(&Bs[k][tx * 8]);
        ulonglong2 b0 = *reinterpret_cast<const ulonglong2*>(Bp + 0);
        ulonglong2 b1 = *reinterpret_cast<const ulonglong2*>(Bp + 2);
        ull av[8] = {a0.x, a0.y, a1.x, a1.y, a2.x, a2.y, a3.x, a3.y};
        ull bv[4] = {b0.x, b0.y, b1.x, b1.y};
#pragma unroll
        for (int r = 0; r < 8; ++r)
#pragma unroll
            for (int c = 0; c < 4; ++c) fma2(acc[r][c], av[r], bv[c]);
    }
}

// ------------------------- K1: gi ------------------------------------------
__global__ void gi_kernel(const float* __restrict__ S, const float* __restrict__ w_ih,
                          const float* __restrict__ b_ih) {
    __shared__ float Ss[HID_];
    int blk = blockIdx.x;
    int o = threadIdx.x;
    if (o < HID_) Ss[o] = S[blk * HID_ + o];
    __syncthreads();
    float acc = b_ih[o];
#pragma unroll 8
    for (int k = 0; k < HID_; k += 4) {
        float4 w = *reinterpret_cast<const float4*>(&w_ih[o * HID_ + k]);
        acc += Ss[k] * w.x + Ss[k + 1] * w.y + Ss[k + 2] * w.z + Ss[k + 3] * w.w;
    }
    g_gi[blk * 384 + o] = acc;
}

// ------------------------- K2: GRU (register weights) ----------------------
__global__ __launch_bounds__(384, 1) void gru_kernel(const float* __restrict__ w_hh,
                                                     const float* __restrict__ b_hh) {
    __shared__ __align__(16) float hs[HID_];
    __shared__ float ghs[384];
    int o = threadIdx.x;

    ull w2[64];
#pragma unroll
    for (int i = 0; i < 64; ++i) {
        float2 v = reinterpret_cast<const float2*>(w_hh)[o * 64 + i];
        w2[i] = pack2(v.x, v.y);
    }
    if (o < HID_) hs[o] = 0.0f;
    float bh = b_hh[o];
    __syncthreads();

    for (int t = 0; t < HW_; ++t) {
        ull acc2 = pack2(bh, 0.0f);
        const ull* h2 = reinterpret_cast<const ull*>(hs);
#pragma unroll
        for (int i = 0; i < 64; ++i) fma2(acc2, h2[i], w2[i]);
        float2 p = unpack2(acc2);
        ghs[o] = p.x + p.y;
        __syncthreads();
        if (o < HID_) {
            float gir = g_gi[t * 384 + o];
            float giz = g_gi[t * 384 + 128 + o];
            float gin = g_gi[t * 384 + 256 + o];
            float r = 1.0f / (1.0f + expf(-(gir + ghs[o])));
            float z = 1.0f / (1.0f + expf(-(giz + ghs[o + 128])));
            float n = tanhf(gin + r * ghs[o + 256]);
            float hn = (1.0f - z) * n + z * hs[o];
            hs[o] = hn;
            g_K[t * HID_ + o] = hn;
        }
        __syncthreads();
    }
}

// ------------------------- K3: MLP layer 1 ---------------------------------
__global__ __launch_bounds__(128) void mlp1_kernel(const float* __restrict__ A,
                                                   const float* __restrict__ S,
                                                   const float* __restrict__ W1,
                                                   const float* __restrict__ b1) {
    __shared__ float2 Xs2[32][64];
    __shared__ float Bs[32][128];
    int rb = blockIdx.x * 64;
    int w = rb >> 7, a0 = rb & 127;
    int tid = threadIdx.x, tx = tid & 15, ty = tid >> 4;
    ull acc[8][4] = {};
    for (int kc = 0; kc < HID_; kc += 32) {
        __syncthreads();
#pragma unroll
        for (int j = 0; j < 4; ++j) {
            int lin = tid + j * 128;
            int r = lin & 63, kq = lin >> 6;
            float4 av = *reinterpret_cast<const float4*>(&A[(a0 + r) * HID_ + kc + kq * 4]);
            float4 sv = *reinterpret_cast<const float4*>(&S[w * HID_ + kc + kq * 4]);
            float v0 = av.x + sv.x, v1 = av.y + sv.y, v2 = av.z + sv.z, v3 = av.w + sv.w;
            Xs2[kq * 4 + 0][r] = make_float2(v0, v0);
            Xs2[kq * 4 + 1][r] = make_float2(v1, v1);
            Xs2[kq * 4 + 2][r] = make_float2(v2, v2);
            Xs2[kq * 4 + 3][r] = make_float2(v3, v3);
        }
#pragma unroll
        for (int j = 0; j < 8; ++j) {
            float4 wv = *reinterpret_cast<const float4*>(&W1[tid * HID_ + kc + j * 4]);
            Bs[j * 4 + 0][tid] = wv.x;
            Bs[j * 4 + 1][tid] = wv.y;
            Bs[j * 4 + 2][tid] = wv.z;
            Bs[j * 4 + 3][tid] = wv.w;
        }
        __syncthreads();
        tile_fma(Xs2, Bs, acc, tx, ty);
    }
    float bb[8];
#pragma unroll
    for (int c = 0; c < 8; ++c) bb[c] = b1[tx * 8 + c];
#pragma unroll
    for (int i = 0; i < 8; ++i) {
        float o[8];
#pragma unroll
        for (int c = 0; c < 4; ++c) {
            float2 f = unpack2(acc[i][c]);
            o[2 * c] = fmaxf(f.x + bb[2 * c], 0.0f);
            o[2 * c + 1] = fmaxf(f.y + bb[2 * c + 1], 0.0f);
        }
        float* dst = &g_Y1[(rb + ty * 8 + i) * HID_ + tx * 8];
        *reinterpret_cast<float4*>(dst) = make_float4(o[0], o[1], o[2], o[3]);
        *reinterpret_cast<float4*>(dst + 4) = make_float4(o[4], o[5], o[6], o[7]);
    }
}

// ------------------------- K4: MLP layer 2 ---------------------------------
__global__ __launch_bounds__(128) void mlp2_kernel(const float* __restrict__ W2,
                                                   const float* __restrict__ b2) {
    __shared__ float2 Xs2[32][64];
    __shared__ float Bs[32][128];
    int rb = blockIdx.x * 64;
    int tid = threadIdx.x, tx = tid & 15, ty = tid >> 4;
    ull acc[8][4] = {};
    for (int kc = 0; kc < HID_; kc += 32) {
        __syncthreads();
#pragma unroll
        for (int j = 0; j < 4; ++j) {
            int lin = tid + j * 128;
            int r = lin & 63, kq = lin >> 6;
            float4 v = *reinterpret_cast<const float4*>(&g_Y1[(rb + r) * HID_ + kc + kq * 4]);
            Xs2[kq * 4 + 0][r] = make_float2(v.x, v.x);
            Xs2[kq * 4 + 1][r] = make_float2(v.y, v.y);
            Xs2[kq * 4 + 2][r] = make_float2(v.z, v.z);
            Xs2[kq * 4 + 3][r] = make_float2(v.w, v.w);
        }
#pragma unroll
        for (int j = 0; j < 8; ++j) {
            float4 wv = *reinterpret_cast<const float4*>(&W2[tid * HID_ + kc + j * 4]);
            Bs[j * 4 + 0][tid] = wv.x;
            Bs[j * 4 + 1][tid] = wv.y;
            Bs[j * 4 + 2][tid] = wv.z;
            Bs[j * 4 + 3][tid] = wv.w;
        }
        __syncthreads();
        tile_fma(Xs2, Bs, acc, tx, ty);
    }
    float bb[8];
#pragma unroll
    for (int c = 0; c < 8; ++c) bb[c] = b2[tx * 8 + c];
#pragma unroll
    for (int i = 0; i < 8; ++i) {
        float o[8];
#pragma unroll
        for (int c = 0; c < 4; ++c) {
            float2 f = unpack2(acc[i][c]);
            o[2 * c] = fmaxf(f.x + bb[2 * c], 0.0f);
            o[2 * c + 1] = fmaxf(f.y + bb[2 * c + 1], 0.0f);
        }
        float* dst = &g_Y2[(rb + ty * 8 + i) * HID_ + tx * 8];
        *reinterpret_cast<float4*>(dst) = make_float4(o[0], o[1], o[2], o[3]);
        *reinterpret_cast<float4*>(dst + 4) = make_float4(o[4], o[5], o[6], o[7]);
    }
}

// ------------------------- K5: logits --------------------------------------
__global__ __launch_bounds__(128) void logits_kernel() {
    __shared__ float2 Xs2[32][64];
    __shared__ float Bs[32][128];
    int s0 = blockIdx.x * 64;
    int w = blockIdx.y;
    int tid = threadIdx.x, tx = tid & 15, ty = tid >> 4;
    ull acc[8][4] = {};
    for (int kc = 0; kc < HID_; kc += 32) {
        __syncthreads();
#pragma unroll
        for (int j = 0; j < 4; ++j) {
            int lin = tid + j * 128;
            int r = lin & 63, kq = lin >> 6;
            float4 v = *reinterpret_cast<const float4*>(&g_K[(s0 + r) * HID_ + kc + kq * 4]);
            Xs2[kq * 4 + 0][r] = make_float2(v.x, v.x);
            Xs2[kq * 4 + 1][r] = make_float2(v.y, v.y);
            Xs2[kq * 4 + 2][r] = make_float2(v.z, v.z);
            Xs2[kq * 4 + 3][r] = make_float2(v.w, v.w);
        }
#pragma unroll
        for (int j = 0; j < 8; ++j) {
            float4 wv =
                *reinterpret_cast<const float4*>(&g_Y2[(w * NA_ + tid) * HID_ + kc + j * 4]);
            Bs[j * 4 + 0][tid] = wv.x;
            Bs[j * 4 + 1][tid] = wv.y;
            Bs[j * 4 + 2][tid] = wv.z;
            Bs[j * 4 + 3][tid] = wv.w;
        }
        __syncthreads();
        tile_fma(Xs2, Bs, acc, tx, ty);
    }
#pragma unroll
    for (int i = 0; i < 8; ++i) {
        float o[8];
#pragma unroll
        for (int c = 0; c < 4; ++c) {
            float2 f = unpack2(acc[i][c]);
            o[2 * c] = f.x;
            o[2 * c + 1] = f.y;
        }
        float* dst = &g_P[((size_t)w * HW_ + s0 + ty * 8 + i) * NA_ + tx * 8];
        *reinterpret_cast<float4*>(dst) = make_float4(o[0], o[1], o[2], o[3]);
        *reinterpret_cast<float4*>(dst + 4) = make_float4(o[4], o[5], o[6], o[7]);
    }
}

// ------------------------- K6: softmax over s ------------------------------
__global__ void softmax_kernel() {
    int w = blockIdx.x, a = threadIdx.x;
    float* base = g_P + (size_t)w * HW_ * NA_ + a;
    float m = -1e30f;
#pragma unroll 8
    for (int s = 0; s < HW_; ++s) m = fmaxf(m, base[s * NA_]);
    float sum = 0.0f;
#pragma unroll 8
    for (int s = 0; s < HW_; ++s) {
        float e = expf(base[s * NA_] - m);
        base[s * NA_] = e;
        sum += e;
    }
    float inv = 1.0f / sum;
#pragma unroll 8
    for (int s = 0; s < HW_; ++s) base[s * NA_] *= inv;
}

// ------------------------- K6b: P transpose + bf16 split -------------------
// g_P[w][s][a] fp32 -> g_Pth/g_Ptl[w][a][s] bf16
__global__ void ptrans_kernel() {
    __shared__ float tbuf[32][33];
    int w = blockIdx.x, s0 = blockIdx.y * 32, a0 = blockIdx.z * 32;
    int tx = threadIdx.x & 31, ty = threadIdx.x >> 5;  // 32x8
#pragma unroll
    for (int r = 0; r < 4; ++r) {
        int s = s0 + ty + r * 8;
        tbuf[ty + r * 8][tx] = g_P[((size_t)w * HW_ + s) * NA_ + a0 + tx];
    }
    __syncthreads();
#pragma unroll
    for (int r = 0; r < 4; ++r) {
        int a = a0 + ty + r * 8;
        float v = tbuf[tx][ty + r * 8];
        __nv_bfloat16 hi = __float2bfloat16(v);
        size_t idx = ((size_t)w * NA_ + a) * HW_ + s0 + tx;
        g_Pth[idx] = hi;
        g_Ptl[idx] = __float2bfloat16(v - __bfloat162float(hi));
    }
}

// ------------------------- K7: rewards + V0 init ---------------------------
__global__ void init_kernel(const float* __restrict__ inputs) {
    int idx = blockIdx.x * blockDim.x + threadIdx.x;  // 512*256
    int row = idx >> 8, s = idx & 255;
    float v = inputs[row * 257 + s];
    g_R[idx] = v;
    g_V[idx] = v;
    __nv_bfloat16 hi = __float2bfloat16(v);
    g_Vh[0][idx] = hi;
    g_Vl[0][idx] = __float2bfloat16(v - __bfloat162float(hi));
}

// ------------------------- K8: Bellman via mma.sync bf16 -------------------
// grid (4 mtiles, 256 w), 256 threads (8 warps). M=128 x N=128(a) x K=256(s).
// 3 products: Vh*Ph + Vh*Pl + Vl*Ph, fp32 accum.
#define KC_      64
#define TSTRIDE_ 144                 // bytes per staged row (64 bf16 + 8 pad)
#define TILE_B_  (128 * TSTRIDE_)    // 18432
#define STAGE_B_ (4 * TILE_B_)       // 73728

__device__ __forceinline__ void load_tile(uint32_t dst, const __nv_bfloat16* src, int tid) {
    // 128 rows x 64 bf16, src row stride 256 elems
#pragma unroll
    for (int i = 0; i < 4; ++i) {
        int lin = tid + i * 256;
        int row = lin >> 3, seg = lin & 7;
        cp_async16(dst + row * TSTRIDE_ + seg * 16, src + (size_t)row * 256 + seg * 8);
    }
}

__global__ __launch_bounds__(256, 1) void bellman_mma(int srcIdx) {
    extern __shared__ char smem[];
    __shared__ float red_s[8][32];
    uint32_t sb = smem_u32(smem);
    int tid = threadIdx.x, wid = tid >> 5, lane = tid & 31;
    int rb = blockIdx.x * 128;
    int w = blockIdx.y;
    int dstIdx = srcIdx ^ 1;
    int wr = wid >> 1, wc = wid & 1;  // warp tile: rows wr*32.., cols wc*64..

    const __nv_bfloat16* vh = g_Vh[srcIdx] + (size_t)rb * 256;
    const __nv_bfloat16* vl = g_Vl[srcIdx] + (size_t)rb * 256;
    const __nv_bfloat16* ph = g_Pth + (size_t)w * NA_ * HW_;
    const __nv_bfloat16* pl = g_Ptl + (size_t)w * NA_ * HW_;

    float acc[2][8][4];
#pragma unroll
    for (int mb = 0; mb < 2; ++mb)
#pragma unroll
        for (int nt = 0; nt < 8; ++nt)
#pragma unroll
            for (int q = 0; q < 4; ++q) acc[mb][nt][q] = 0.0f;

    // prologue: chunks 0, 1
#pragma unroll
    for (int c = 0; c < 2; ++c) {
        uint32_t st = sb + c * STAGE_B_;
        load_tile(st + 0 * TILE_B_, vh + c * KC_, tid);
        load_tile(st + 1 * TILE_B_, vl + c * KC_, tid);
        load_tile(st + 2 * TILE_B_, ph + c * KC_, tid);
        load_tile(st + 3 * TILE_B_, pl + c * KC_, tid);
        CP_COMMIT();
    }

#pragma unroll
    for (int c = 0; c < 4; ++c) {
        if (c < 3)
            asm volatile("cp.async.wait_group 1;" ::: "memory");
        else
            asm volatile("cp.async.wait_group 0;" ::: "memory");
        __syncthreads();
        uint32_t st = sb + (c & 1) * STAGE_B_;
        uint32_t vhB = st, vlB = st + TILE_B_, phB = st + 2 * TILE_B_, plB = st + 3 * TILE_B_;

#pragma unroll
        for (int kk = 0; kk < 4; ++kk) {
            int koff = kk * 32;  // bytes (16 bf16)
            // A fragments: rows wr*32 + mb*16 + (lane&15), k-half by lane>>4
            uint32_t ah[2][4], al[2][4];
#pragma unroll
            for (int mb = 0; mb < 2; ++mb) {
                uint32_t roff = (wr * 32 + mb * 16 + (lane & 15)) * TSTRIDE_ +
                                (lane >> 4) * 16 + koff;
                ldsm_x4(ah[mb], vhB + roff);
                ldsm_x4(al[mb], vlB + roff);
            }
            // B fragments: n = wc*64 + np*16 + (lane>>4)*8 + (lane&7)
            uint32_t bh[8][2], bl[8][2];
#pragma unroll
            for (int np = 0; np < 4; ++np) {
                uint32_t n = wc * 64 + np * 16 + ((lane >> 4) << 3) + (lane & 7);
                uint32_t off = n * TSTRIDE_ + ((lane >> 3) & 1) * 16 + koff;
                uint32_t r[4];
                ldsm_x4(r, phB + off);
                bh[np * 2][0] = r[0]; bh[np * 2][1] = r[1];
                bh[np * 2 + 1][0] = r[2]; bh[np * 2 + 1][1] = r[3];
                ldsm_x4(r, plB + off);
                bl[np * 2][0] = r[0]; bl[np * 2][1] = r[1];
                bl[np * 2 + 1][0] = r[2]; bl[np * 2 + 1][1] = r[3];
            }
#pragma unroll
            for (int mb = 0; mb < 2; ++mb)
#pragma unroll
                for (int nt = 0; nt < 8; ++nt) {
                    mma16816(acc[mb][nt], ah[mb], bh[nt]);
                    mma16816(acc[mb][nt], ah[mb], bl[nt]);
                    mma16816(acc[mb][nt], al[mb], bh[nt]);
                }
        }
        __syncthreads();
        if (c < 2) {
            uint32_t stn = sb + (c & 1) * STAGE_B_;
            int kc = (c + 2) * KC_;
            load_tile(stn + 0 * TILE_B_, vh + kc, tid);
            load_tile(stn + 1 * TILE_B_, vl + kc, tid);
            load_tile(stn + 2 * TILE_B_, ph + kc, tid);
            load_tile(stn + 3 * TILE_B_, pl + kc, tid);
            CP_COMMIT();
        }
    }

    // epilogue: max over n within thread, then quad shfl, then cross-warp smem
    int g = lane >> 2;
#pragma unroll
    for (int mb = 0; mb < 2; ++mb) {
        float mA = -1e30f, mB = -1e30f;
#pragma unroll
        for (int nt = 0; nt < 8; ++nt) {
            mA = fmaxf(mA, fmaxf(acc[mb][nt][0], acc[mb][nt][1]));
            mB = fmaxf(mB, fmaxf(acc[mb][nt][2], acc[mb][nt][3]));
        }
        mA = fmaxf(mA, __shfl_xor_sync(0xffffffffu, mA, 1));
        mA = fmaxf(mA, __shfl_xor_sync(0xffffffffu, mA, 2));
        mB = fmaxf(mB, __shfl_xor_sync(0xffffffffu, mB, 1));
        mB = fmaxf(mB, __shfl_xor_sync(0xffffffffu, mB, 2));
        if ((lane & 3) == 0) {
            red_s[wid][mb * 16 + g] = mA;
            red_s[wid][mb * 16 + 8 + g] = mB;
        }
    }
    __syncthreads();
    if (tid < 128) {
        int r = tid;
        int wrr = r >> 5, rl = r & 31;
        float m = fmaxf(red_s[wrr * 2][rl], red_s[wrr * 2 + 1][rl]);
        int row = rb + r;
        float v = g_R[row * HW_ + w] + m;
        g_V[row * HW_ + w] = v;
        __nv_bfloat16 hi = __float2bfloat16(v);
        g_Vh[dstIdx][row * HW_ + w] = hi;
        g_Vl[dstIdx][row * HW_ + w] = __float2bfloat16(v - __bfloat162float(hi));
    }
}

// ------------------------- K9: output assembly -----------------------------
__global__ void assemble_kernel(const float* __restrict__ rnn_hxs, float* __restrict__ out,
                                int out_size) {
    int idx = blockIdx.x * blockDim.x + threadIdx.x;
    if (idx >= out_size || idx >= OUTT_) return;
    int row, c;
    if (idx < OUT1_) {
        row = idx / HX_;
        c = idx - row * HX_;
    } else {
        int k = idx - OUT1_;
        int r2 = k / HX_;
        c = k - r2 * HX_;
        row = 448 + r2;
    }
    float v = (c < PASS_) ? rnn_hxs[row * HX_ + c] : g_V[row * HW_ + (c - PASS_)];
    out[idx] = v;
}

// ------------------------- launcher ----------------------------------------
extern "C" void kernel_launch(void* const* d_in, const int* in_sizes, int n_in,
                              void* d_out, int out_size) {
    const float* inputs = (const float*)d_in[0];
    const float* rnn_hxs = (const float*)d_in[1];
    const float* S = (const float*)d_in[2];
    const float* A = (const float*)d_in[3];
    const float* w_ih = (const float*)d_in[4];
    const float* w_hh = (const float*)d_in[5];
    const float* b_ih = (const float*)d_in[6];
    const float* b_hh = (const float*)d_in[7];
    const float* W1 = (const float*)d_in[8];
    const float* b1 = (const float*)d_in[9];
    const float* W2 = (const float*)d_in[10];
    const float* b2 = (const float*)d_in[11];
    float* out = (float*)d_out;

    const int BSMEM = 2 * STAGE_B_;  // 147456
    cudaFuncSetAttribute(bellman_mma, cudaFuncAttributeMaxDynamicSharedMemorySize, BSMEM);

    gi_kernel<<<HW_, 384>>>(S, w_ih, b_ih);
    gru_kernel<<<1, 384>>>(w_hh, b_hh);
    mlp1_kernel<<<HW_ * NA_ / 64, 128>>>(A, S, W1, b1);
    mlp2_kernel<<<HW_ * NA_ / 64, 128>>>(W2, b2);
    logits_kernel<<<dim3(4, HW_), 128>>>();
    softmax_kernel<<<HW_, 128>>>();
    ptrans_kernel<<<dim3(HW_, 8, 4), 256>>>();
    init_kernel<<<ROWS_, 256>>>(inputs);
    for (int it = 0; it < 15; ++it) {
        bellman_mma<<<dim3(4, 256), 256, BSMEM>>>(it & 1);
    }
    int total = out_size < OUTT_ ? out_size : OUTT_;
    assemble_kernel<<<(total + 255) / 256, 256>>>(rnn_hxs, out, out_size);
}

// round 5
// speedup vs baseline: 2.8198x; 1.0910x over previous
#include <cuda_runtime.h>
#include <cuda_bf16.h>
#include <math.h>
#include <stdint.h>

// Problem constants
#define T_      8
#define N_      64
#define HW_     256
#define HID_    128
#define NA_     128
#define HX_     514
#define PASS_   258
#define ROWS_   512
#define OUT1_   263168
#define OUTT_   296064

typedef unsigned long long ull;

// ------------------------- scratch (device globals; no allocs) -------------
__device__ float g_gi[HW_ * 384];
__device__ __nv_bfloat16 g_Kh[HW_ * HID_];
__device__ __nv_bfloat16 g_Kl[HW_ * HID_];
__device__ float g_Y1[HW_ * NA_ * HID_];
__device__ __nv_bfloat16 g_Y2h[HW_ * NA_ * HID_];
__device__ __nv_bfloat16 g_Y2l[HW_ * NA_ * HID_];
__device__ float g_P[HW_ * HW_ * NA_];                    // P[w][s][a] fp32
__device__ __nv_bfloat16 g_Pth[(size_t)HW_ * NA_ * HW_];  // [w][a][s] hi
__device__ __nv_bfloat16 g_Ptl[(size_t)HW_ * NA_ * HW_];  // [w][a][s] lo
__device__ float g_R[ROWS_ * HW_];
__device__ float g_V[ROWS_ * HW_];                        // fp32 (final)
__device__ __nv_bfloat16 g_Vh[2][ROWS_ * HW_];
__device__ __nv_bfloat16 g_Vl[2][ROWS_ * HW_];

// ------------------------- ptx helpers -------------------------------------
__device__ __forceinline__ void fma2(ull& d, ull a, ull b) {
    asm("fma.rn.f32x2 %0, %1, %2, %0;" : "+l"(d) : "l"(a), "l"(b));
}
__device__ __forceinline__ float2 unpack2(ull u) {
    float2 f;
    asm("mov.b64 {%0, %1}, %2;" : "=f"(f.x), "=f"(f.y) : "l"(u));
    return f;
}
__device__ __forceinline__ ull pack2(float x, float y) {
    ull u;
    asm("mov.b64 %0, {%1, %2};" : "=l"(u) : "f"(x), "f"(y));
    return u;
}
__device__ __forceinline__ uint32_t smem_u32(const void* p) {
    uint32_t a;
    asm("{ .reg .u64 t; cvta.to.shared.u64 t, %1; cvt.u32.u64 %0, t; }" : "=r"(a) : "l"(p));
    return a;
}
__device__ __forceinline__ void cp_async16(uint32_t dst, const void* src) {
    asm volatile("cp.async.cg.shared.global [%0], [%1], 16;" ::"r"(dst), "l"(src) : "memory");
}
#define CP_COMMIT() asm volatile("cp.async.commit_group;" ::: "memory")

__device__ __forceinline__ void ldsm_x4(uint32_t* r, uint32_t addr) {
    asm volatile("ldmatrix.sync.aligned.m8n8.x4.shared.b16 {%0,%1,%2,%3}, [%4];"
                 : "=r"(r[0]), "=r"(r[1]), "=r"(r[2]), "=r"(r[3]) : "r"(addr));
}
__device__ __forceinline__ void mma16816(float* c, const uint32_t* a, const uint32_t* b) {
    asm volatile(
        "mma.sync.aligned.m16n8k16.row.col.f32.bf16.bf16.f32 "
        "{%0,%1,%2,%3}, {%4,%5,%6,%7}, {%8,%9}, {%0,%1,%2,%3};"
        : "+f"(c[0]), "+f"(c[1]), "+f"(c[2]), "+f"(c[3])
        : "r"(a[0]), "r"(a[1]), "r"(a[2]), "r"(a[3]), "r"(b[0]), "r"(b[1]));
}

// swizzled 16KB tile: 128 rows x 64 bf16 (128B rows), seg16 c: addr = r*128 + ((c ^ (r&7))<<4)
#define TILE16 16384
__device__ __forceinline__ uint32_t sw_addr(uint32_t base, int r, int c16) {
    return base + r * 128 + (((uint32_t)(c16 ^ (r & 7))) << 4);
}
__device__ __forceinline__ void load_tile_sw(uint32_t dst, const __nv_bfloat16* src, int stride,
                                             int tid) {
#pragma unroll
    for (int i = 0; i < 4; ++i) {
        int lin = tid + i * 256;
        int r = lin >> 3, seg = lin & 7;
        cp_async16(sw_addr(dst, r, seg), src + (size_t)r * stride + seg * 8);
    }
}

// ------------------------- f32x2 tile core (mlp) ---------------------------
__device__ __forceinline__ void tile_fma(const float2 (&Xs2)[32][64], const float (&Bs)[32][128],
                                         ull (&acc)[8][4], int tx, int ty) {
    const ull* Xu = reinterpret_cast<const ull*>(&Xs2[0][0]);
#pragma unroll 8
    for (int k = 0; k < 32; ++k) {
        ulonglong2 a0 = *reinterpret_cast<const ulonglong2*>(Xu + k * 64 + ty * 8 + 0);
        ulonglong2 a1 = *reinterpret_cast<const ulonglong2*>(Xu + k * 64 + ty * 8 + 2);
        ulonglong2 a2 = *reinterpret_cast<const ulonglong2*>(Xu + k * 64 + ty * 8 + 4);
        ulonglong2 a3 = *reinterpret_cast<const ulonglong2*>(Xu + k * 64 + ty * 8 + 6);
        const ull* Bp = reinterpret_cast<const ull*>(&Bs[k][tx * 8]);
        ulonglong2 b0 = *reinterpret_cast<const ulonglong2*>(Bp + 0);
        ulonglong2 b1 = *reinterpret_cast<const ulonglong2*>(Bp + 2);
        ull av[8] = {a0.x, a0.y, a1.x, a1.y, a2.x, a2.y, a3.x, a3.y};
        ull bv[4] = {b0.x, b0.y, b1.x, b1.y};
#pragma unroll
        for (int r = 0; r < 8; ++r)
#pragma unroll
            for (int c = 0; c < 4; ++c) fma2(acc[r][c], av[r], bv[c]);
    }
}

// ------------------------- K1: gi ------------------------------------------
__global__ void gi_kernel(const float* __restrict__ S, const float* __restrict__ w_ih,
                          const float* __restrict__ b_ih) {
    __shared__ float Ss[HID_];
    int blk = blockIdx.x;
    int o = threadIdx.x;
    if (o < HID_) Ss[o] = S[blk * HID_ + o];
    __syncthreads();
    float acc = b_ih[o];
#pragma unroll 8
    for (int k = 0; k < HID_; k += 4) {
        float4 w = *reinterpret_cast<const float4*>(&w_ih[o * HID_ + k]);
        acc += Ss[k] * w.x + Ss[k + 1] * w.y + Ss[k + 2] * w.z + Ss[k + 3] * w.w;
    }
    g_gi[blk * 384 + o] = acc;
}

// ------------------------- K2: GRU (register weights) ----------------------
__global__ __launch_bounds__(384, 1) void gru_kernel(const float* __restrict__ w_hh,
                                                     const float* __restrict__ b_hh) {
    __shared__ __align__(16) float hs[HID_];
    __shared__ float ghs[384];
    int o = threadIdx.x;

    ull w2[64];
#pragma unroll
    for (int i = 0; i < 64; ++i) {
        float2 v = reinterpret_cast<const float2*>(w_hh)[o * 64 + i];
        w2[i] = pack2(v.x, v.y);
    }
    if (o < HID_) hs[o] = 0.0f;
    float bh = b_hh[o];
    __syncthreads();

    for (int t = 0; t < HW_; ++t) {
        ull acc2 = pack2(bh, 0.0f);
        const ull* h2 = reinterpret_cast<const ull*>(hs);
#pragma unroll
        for (int i = 0; i < 64; ++i) fma2(acc2, h2[i], w2[i]);
        float2 p = unpack2(acc2);
        ghs[o] = p.x + p.y;
        __syncthreads();
        if (o < HID_) {
            float gir = g_gi[t * 384 + o];
            float giz = g_gi[t * 384 + 128 + o];
            float gin = g_gi[t * 384 + 256 + o];
            float r = 1.0f / (1.0f + expf(-(gir + ghs[o])));
            float z = 1.0f / (1.0f + expf(-(giz + ghs[o + 128])));
            float n = tanhf(gin + r * ghs[o + 256]);
            float hn = (1.0f - z) * n + z * hs[o];
            hs[o] = hn;
            __nv_bfloat16 hi = __float2bfloat16(hn);
            g_Kh[t * HID_ + o] = hi;
            g_Kl[t * HID_ + o] = __float2bfloat16(hn - __bfloat162float(hi));
        }
        __syncthreads();
    }
}

// ------------------------- K3: MLP layer 1 ---------------------------------
__global__ __launch_bounds__(128) void mlp1_kernel(const float* __restrict__ A,
                                                   const float* __restrict__ S,
                                                   const float* __restrict__ W1,
                                                   const float* __restrict__ b1) {
    __shared__ float2 Xs2[32][64];
    __shared__ float Bs[32][128];
    int rb = blockIdx.x * 64;
    int w = rb >> 7, a0 = rb & 127;
    int tid = threadIdx.x, tx = tid & 15, ty = tid >> 4;
    ull acc[8][4] = {};
    for (int kc = 0; kc < HID_; kc += 32) {
        __syncthreads();
#pragma unroll
        for (int j = 0; j < 4; ++j) {
            int lin = tid + j * 128;
            int r = lin & 63, kq = lin >> 6;
            float4 av = *reinterpret_cast<const float4*>(&A[(a0 + r) * HID_ + kc + kq * 4]);
            float4 sv = *reinterpret_cast<const float4*>(&S[w * HID_ + kc + kq * 4]);
            float v0 = av.x + sv.x, v1 = av.y + sv.y, v2 = av.z + sv.z, v3 = av.w + sv.w;
            Xs2[kq * 4 + 0][r] = make_float2(v0, v0);
            Xs2[kq * 4 + 1][r] = make_float2(v1, v1);
            Xs2[kq * 4 + 2][r] = make_float2(v2, v2);
            Xs2[kq * 4 + 3][r] = make_float2(v3, v3);
        }
#pragma unroll
        for (int j = 0; j < 8; ++j) {
            float4 wv = *reinterpret_cast<const float4*>(&W1[tid * HID_ + kc + j * 4]);
            Bs[j * 4 + 0][tid] = wv.x;
            Bs[j * 4 + 1][tid] = wv.y;
            Bs[j * 4 + 2][tid] = wv.z;
            Bs[j * 4 + 3][tid] = wv.w;
        }
        __syncthreads();
        tile_fma(Xs2, Bs, acc, tx, ty);
    }
    float bb[8];
#pragma unroll
    for (int c = 0; c < 8; ++c) bb[c] = b1[tx * 8 + c];
#pragma unroll
    for (int i = 0; i < 8; ++i) {
        float o[8];
#pragma unroll
        for (int c = 0; c < 4; ++c) {
            float2 f = unpack2(acc[i][c]);
            o[2 * c] = fmaxf(f.x + bb[2 * c], 0.0f);
            o[2 * c + 1] = fmaxf(f.y + bb[2 * c + 1], 0.0f);
        }
        float* dst = &g_Y1[(rb + ty * 8 + i) * HID_ + tx * 8];
        *reinterpret_cast<float4*>(dst) = make_float4(o[0], o[1], o[2], o[3]);
        *reinterpret_cast<float4*>(dst + 4) = make_float4(o[4], o[5], o[6], o[7]);
    }
}

// ------------------------- K4: MLP layer 2 (writes bf16 split) -------------
__global__ __launch_bounds__(128) void mlp2_kernel(const float* __restrict__ W2,
                                                   const float* __restrict__ b2) {
    __shared__ float2 Xs2[32][64];
    __shared__ float Bs[32][128];
    int rb = blockIdx.x * 64;
    int tid = threadIdx.x, tx = tid & 15, ty = tid >> 4;
    ull acc[8][4] = {};
    for (int kc = 0; kc < HID_; kc += 32) {
        __syncthreads();
#pragma unroll
        for (int j = 0; j < 4; ++j) {
            int lin = tid + j * 128;
            int r = lin & 63, kq = lin >> 6;
            float4 v = *reinterpret_cast<const float4*>(&g_Y1[(rb + r) * HID_ + kc + kq * 4]);
            Xs2[kq * 4 + 0][r] = make_float2(v.x, v.x);
            Xs2[kq * 4 + 1][r] = make_float2(v.y, v.y);
            Xs2[kq * 4 + 2][r] = make_float2(v.z, v.z);
            Xs2[kq * 4 + 3][r] = make_float2(v.w, v.w);
        }
#pragma unroll
        for (int j = 0; j < 8; ++j) {
            float4 wv = *reinterpret_cast<const float4*>(&W2[tid * HID_ + kc + j * 4]);
            Bs[j * 4 + 0][tid] = wv.x;
            Bs[j * 4 + 1][tid] = wv.y;
            Bs[j * 4 + 2][tid] = wv.z;
            Bs[j * 4 + 3][tid] = wv.w;
        }
        __syncthreads();
        tile_fma(Xs2, Bs, acc, tx, ty);
    }
    float bb[8];
#pragma unroll
    for (int c = 0; c < 8; ++c) bb[c] = b2[tx * 8 + c];
#pragma unroll
    for (int i = 0; i < 8; ++i) {
        __nv_bfloat16 h8[8], l8[8];
#pragma unroll
        for (int c = 0; c < 4; ++c) {
            float2 f = unpack2(acc[i][c]);
            float o0 = fmaxf(f.x + bb[2 * c], 0.0f);
            float o1 = fmaxf(f.y + bb[2 * c + 1], 0.0f);
            h8[2 * c] = __float2bfloat16(o0);
            l8[2 * c] = __float2bfloat16(o0 - __bfloat162float(h8[2 * c]));
            h8[2 * c + 1] = __float2bfloat16(o1);
            l8[2 * c + 1] = __float2bfloat16(o1 - __bfloat162float(h8[2 * c + 1]));
        }
        size_t off = (size_t)(rb + ty * 8 + i) * HID_ + tx * 8;
        *reinterpret_cast<uint4*>(&g_Y2h[off]) = *reinterpret_cast<uint4*>(h8);
        *reinterpret_cast<uint4*>(&g_Y2l[off]) = *reinterpret_cast<uint4*>(l8);
    }
}

// ------------------------- K5: logits via mma.sync -------------------------
// grid (2 stiles, 256 w), 256 threads. L[w][s][a] = K[s,:].Y2[(w,a),:], 3-prod split.
__global__ __launch_bounds__(256, 1) void logits_mma() {
    extern __shared__ char smem[];
    uint32_t sb = smem_u32(smem);
    int tid = threadIdx.x, wid = tid >> 5, lane = tid & 31;
    int s0 = blockIdx.x * 128;
    int w = blockIdx.y;
    int wr = wid >> 1, wc = wid & 1;

    // tiles: Kh c0,c1 | Kl c0,c1 | Yh c0,c1 | Yl c0,c1
#pragma unroll
    for (int c = 0; c < 2; ++c) {
        load_tile_sw(sb + (0 * 2 + c) * TILE16, g_Kh + (size_t)s0 * 128 + c * 64, 128, tid);
        load_tile_sw(sb + (1 * 2 + c) * TILE16, g_Kl + (size_t)s0 * 128 + c * 64, 128, tid);
        load_tile_sw(sb + (2 * 2 + c) * TILE16, g_Y2h + (size_t)w * 128 * 128 + c * 64, 128, tid);
        load_tile_sw(sb + (3 * 2 + c) * TILE16, g_Y2l + (size_t)w * 128 * 128 + c * 64, 128, tid);
    }
    CP_COMMIT();
    asm volatile("cp.async.wait_group 0;" ::: "memory");
    __syncthreads();

    float acc[2][8][4];
#pragma unroll
    for (int mb = 0; mb < 2; ++mb)
#pragma unroll
        for (int nt = 0; nt < 8; ++nt)
#pragma unroll
            for (int q = 0; q < 4; ++q) acc[mb][nt][q] = 0.0f;

#pragma unroll
    for (int c = 0; c < 2; ++c) {
        uint32_t ahT = sb + c * TILE16, alT = sb + (2 + c) * TILE16;
        uint32_t bhT = sb + (4 + c) * TILE16, blT = sb + (6 + c) * TILE16;
#pragma unroll
        for (int kk = 0; kk < 4; ++kk) {
            uint32_t ah[2][4], al[2][4];
#pragma unroll
            for (int mb = 0; mb < 2; ++mb) {
                int r = wr * 32 + mb * 16 + (lane & 15);
                int c16 = (lane >> 4) + kk * 2;
                ldsm_x4(ah[mb], sw_addr(ahT, r, c16));
                ldsm_x4(al[mb], sw_addr(alT, r, c16));
            }
            uint32_t bh[8][2], bl[8][2];
#pragma unroll
            for (int np = 0; np < 4; ++np) {
                int n = wc * 64 + np * 16 + ((lane >> 4) << 3) + (lane & 7);
                int c16 = ((lane >> 3) & 1) + kk * 2;
                uint32_t r4[4];
                ldsm_x4(r4, sw_addr(bhT, n, c16));
                bh[np * 2][0] = r4[0]; bh[np * 2][1] = r4[1];
                bh[np * 2 + 1][0] = r4[2]; bh[np * 2 + 1][1] = r4[3];
                ldsm_x4(r4, sw_addr(blT, n, c16));
                bl[np * 2][0] = r4[0]; bl[np * 2][1] = r4[1];
                bl[np * 2 + 1][0] = r4[2]; bl[np * 2 + 1][1] = r4[3];
            }
#pragma unroll
            for (int mb = 0; mb < 2; ++mb)
#pragma unroll
                for (int nt = 0; nt < 8; ++nt) {
                    mma16816(acc[mb][nt], ah[mb], bh[nt]);
                    mma16816(acc[mb][nt], ah[mb], bl[nt]);
                    mma16816(acc[mb][nt], al[mb], bh[nt]);
                }
        }
    }
    int g = lane >> 2;
#pragma unroll
    for (int mb = 0; mb < 2; ++mb)
#pragma unroll
        for (int nt = 0; nt < 8; ++nt) {
            int row = wr * 32 + mb * 16 + g;
            int col = wc * 64 + nt * 8 + (lane & 3) * 2;
            float* d0 = &g_P[((size_t)w * HW_ + s0 + row) * NA_ + col];
            *reinterpret_cast<float2*>(d0) = make_float2(acc[mb][nt][0], acc[mb][nt][1]);
            float* d1 = &g_P[((size_t)w * HW_ + s0 + row + 8) * NA_ + col];
            *reinterpret_cast<float2*>(d1) = make_float2(acc[mb][nt][2], acc[mb][nt][3]);
        }
}

// ------------------------- K6: softmax over s ------------------------------
__global__ void softmax_kernel() {
    int w = blockIdx.x, a = threadIdx.x;
    float* base = g_P + (size_t)w * HW_ * NA_ + a;
    float m = -1e30f;
#pragma unroll 8
    for (int s = 0; s < HW_; ++s) m = fmaxf(m, base[s * NA_]);
    float sum = 0.0f;
#pragma unroll 8
    for (int s = 0; s < HW_; ++s) {
        float e = expf(base[s * NA_] - m);
        base[s * NA_] = e;
        sum += e;
    }
    float inv = 1.0f / sum;
#pragma unroll 8
    for (int s = 0; s < HW_; ++s) base[s * NA_] *= inv;
}

// ------------------------- K6b: P transpose + bf16 split -------------------
__global__ void ptrans_kernel() {
    __shared__ float tbuf[32][33];
    int w = blockIdx.x, s0 = blockIdx.y * 32, a0 = blockIdx.z * 32;
    int tx = threadIdx.x & 31, ty = threadIdx.x >> 5;  // 32x8
#pragma unroll
    for (int r = 0; r < 4; ++r) {
        int s = s0 + ty + r * 8;
        tbuf[ty + r * 8][tx] = g_P[((size_t)w * HW_ + s) * NA_ + a0 + tx];
    }
    __syncthreads();
#pragma unroll
    for (int r = 0; r < 4; ++r) {
        int a = a0 + ty + r * 8;
        float v = tbuf[tx][ty + r * 8];
        __nv_bfloat16 hi = __float2bfloat16(v);
        size_t idx = ((size_t)w * NA_ + a) * HW_ + s0 + tx;
        g_Pth[idx] = hi;
        g_Ptl[idx] = __float2bfloat16(v - __bfloat162float(hi));
    }
}

// ------------------------- K7: rewards + V0 init ---------------------------
__global__ void init_kernel(const float* __restrict__ inputs) {
    int idx = blockIdx.x * blockDim.x + threadIdx.x;  // 512*256
    int row = idx >> 8, s = idx & 255;
    float v = inputs[row * 257 + s];
    g_R[idx] = v;
    g_V[idx] = v;
    __nv_bfloat16 hi = __float2bfloat16(v);
    g_Vh[0][idx] = hi;
    g_Vl[0][idx] = __float2bfloat16(v - __bfloat162float(hi));
}

// ------------------------- K8: Bellman (V-resident, streamed P) ------------
// grid (4 mtiles, 64 w-groups), 256 thr. Per CTA: V hi/lo K=256 in smem once;
// 16 P-chunk iterations (4 w x 4 chunks), 2-stage double buffer.
// smem: Vh c0..3 [0,64K) | Vl c0..3 [64K,128K) | P stages [128K,192K)
#define BVOFF_  65536
#define BPOFF_  131072
#define BSMEM_  196608

__global__ __launch_bounds__(256, 1) void bellman_mma(int srcIdx) {
    extern __shared__ char smem[];
    __shared__ float red_s[8][32];
    uint32_t sb = smem_u32(smem);
    int tid = threadIdx.x, wid = tid >> 5, lane = tid & 31;
    int rb = blockIdx.x * 128;
    int wg = blockIdx.y * 4;
    int dstIdx = srcIdx ^ 1;
    int wr = wid >> 1, wc = wid & 1;

    const __nv_bfloat16* vh = g_Vh[srcIdx] + (size_t)rb * 256;
    const __nv_bfloat16* vl = g_Vl[srcIdx] + (size_t)rb * 256;

    // prologue: V (8 tiles) + P chunk0 -> group0 ; P chunk1 -> group1
#pragma unroll
    for (int c = 0; c < 4; ++c) {
        load_tile_sw(sb + c * TILE16, vh + c * 64, 256, tid);
        load_tile_sw(sb + BVOFF_ + c * TILE16, vl + c * 64, 256, tid);
    }
    load_tile_sw(sb + BPOFF_, g_Pth + (size_t)wg * 32768, 256, tid);
    load_tile_sw(sb + BPOFF_ + TILE16, g_Ptl + (size_t)wg * 32768, 256, tid);
    CP_COMMIT();
    load_tile_sw(sb + BPOFF_ + 32768, g_Pth + (size_t)wg * 32768 + 64, 256, tid);
    load_tile_sw(sb + BPOFF_ + 32768 + TILE16, g_Ptl + (size_t)wg * 32768 + 64, 256, tid);
    CP_COMMIT();

    float acc[2][8][4];
#pragma unroll
    for (int mb = 0; mb < 2; ++mb)
#pragma unroll
        for (int nt = 0; nt < 8; ++nt)
#pragma unroll
            for (int q = 0; q < 4; ++q) acc[mb][nt][q] = 0.0f;

    for (int i = 0; i < 16; ++i) {
        if (i < 15)
            asm volatile("cp.async.wait_group 1;" ::: "memory");
        else
            asm volatile("cp.async.wait_group 0;" ::: "memory");
        __syncthreads();

        int c = i & 3;
        uint32_t vhT = sb + c * TILE16, vlT = sb + BVOFF_ + c * TILE16;
        uint32_t phT = sb + BPOFF_ + (i & 1) * 32768, plT = phT + TILE16;

#pragma unroll
        for (int kk = 0; kk < 4; ++kk) {
            uint32_t ah[2][4], al[2][4];
#pragma unroll
            for (int mb = 0; mb < 2; ++mb) {
                int r = wr * 32 + mb * 16 + (lane & 15);
                int c16 = (lane >> 4) + kk * 2;
                ldsm_x4(ah[mb], sw_addr(vhT, r, c16));
                ldsm_x4(al[mb], sw_addr(vlT, r, c16));
            }
            uint32_t bh[8][2], bl[8][2];
#pragma unroll
            for (int np = 0; np < 4; ++np) {
                int n = wc * 64 + np * 16 + ((lane >> 4) << 3) + (lane & 7);
                int c16 = ((lane >> 3) & 1) + kk * 2;
                uint32_t r4[4];
                ldsm_x4(r4, sw_addr(phT, n, c16));
                bh[np * 2][0] = r4[0]; bh[np * 2][1] = r4[1];
                bh[np * 2 + 1][0] = r4[2]; bh[np * 2 + 1][1] = r4[3];
                ldsm_x4(r4, sw_addr(plT, n, c16));
                bl[np * 2][0] = r4[0]; bl[np * 2][1] = r4[1];
                bl[np * 2 + 1][0] = r4[2]; bl[np * 2 + 1][1] = r4[3];
            }
#pragma unroll
            for (int mb = 0; mb < 2; ++mb)
#pragma unroll
                for (int nt = 0; nt < 8; ++nt) {
                    mma16816(acc[mb][nt], ah[mb], bh[nt]);
                    mma16816(acc[mb][nt], ah[mb], bl[nt]);
                    mma16816(acc[mb][nt], al[mb], bh[nt]);
                }
        }
        __syncthreads();

        if (i < 14) {
            int nx = i + 2;
            int wn = wg + (nx >> 2), cn = nx & 3;
            uint32_t st = sb + BPOFF_ + (i & 1) * 32768;
            load_tile_sw(st, g_Pth + (size_t)wn * 32768 + cn * 64, 256, tid);
            load_tile_sw(st + TILE16, g_Ptl + (size_t)wn * 32768 + cn * 64, 256, tid);
            CP_COMMIT();
        }

        if (c == 3) {
            int w = wg + (i >> 2);
            int g = lane >> 2;
#pragma unroll
            for (int mb = 0; mb < 2; ++mb) {
                float mA = -1e30f, mB = -1e30f;
#pragma unroll
                for (int nt = 0; nt < 8; ++nt) {
                    mA = fmaxf(mA, fmaxf(acc[mb][nt][0], acc[mb][nt][1]));
                    mB = fmaxf(mB, fmaxf(acc[mb][nt][2], acc[mb][nt][3]));
                }
                mA = fmaxf(mA, __shfl_xor_sync(0xffffffffu, mA, 1));
                mA = fmaxf(mA, __shfl_xor_sync(0xffffffffu, mA, 2));
                mB = fmaxf(mB, __shfl_xor_sync(0xffffffffu, mB, 1));
                mB = fmaxf(mB, __shfl_xor_sync(0xffffffffu, mB, 2));
                if ((lane & 3) == 0) {
                    red_s[wid][mb * 16 + g] = mA;
                    red_s[wid][mb * 16 + 8 + g] = mB;
                }
            }
            __syncthreads();
            if (tid < 128) {
                int wrr = tid >> 5, rl = tid & 31;
                float m = fmaxf(red_s[wrr * 2][rl], red_s[wrr * 2 + 1][rl]);
                int row = rb + tid;
                float v = g_R[row * HW_ + w] + m;
                g_V[row * HW_ + w] = v;
                __nv_bfloat16 hi = __float2bfloat16(v);
                g_Vh[dstIdx][row * HW_ + w] = hi;
                g_Vl[dstIdx][row * HW_ + w] = __float2bfloat16(v - __bfloat162float(hi));
            }
#pragma unroll
            for (int mb = 0; mb < 2; ++mb)
#pragma unroll
                for (int nt = 0; nt < 8; ++nt)
#pragma unroll
                    for (int q = 0; q < 4; ++q) acc[mb][nt][q] = 0.0f;
        }
    }
}

// ------------------------- K9: output assembly -----------------------------
__global__ void assemble_kernel(const float* __restrict__ rnn_hxs, float* __restrict__ out,
                                int out_size) {
    int idx = blockIdx.x * blockDim.x + threadIdx.x;
    if (idx >= out_size || idx >= OUTT_) return;
    int row, c;
    if (idx < OUT1_) {
        row = idx / HX_;
        c = idx - row * HX_;
    } else {
        int k = idx - OUT1_;
        int r2 = k / HX_;
        c = k - r2 * HX_;
        row = 448 + r2;
    }
    float v = (c < PASS_) ? rnn_hxs[row * HX_ + c] : g_V[row * HW_ + (c - PASS_)];
    out[idx] = v;
}

// ------------------------- launcher ----------------------------------------
extern "C" void kernel_launch(void* const* d_in, const int* in_sizes, int n_in,
                              void* d_out, int out_size) {
    const float* inputs = (const float*)d_in[0];
    const float* rnn_hxs = (const float*)d_in[1];
    const float* S = (const float*)d_in[2];
    const float* A = (const float*)d_in[3];
    const float* w_ih = (const float*)d_in[4];
    const float* w_hh = (const float*)d_in[5];
    const float* b_ih = (const float*)d_in[6];
    const float* b_hh = (const float*)d_in[7];
    const float* W1 = (const float*)d_in[8];
    const float* b1 = (const float*)d_in[9];
    const float* W2 = (const float*)d_in[10];
    const float* b2 = (const float*)d_in[11];
    float* out = (float*)d_out;

    cudaFuncSetAttribute(bellman_mma, cudaFuncAttributeMaxDynamicSharedMemorySize, BSMEM_);
    cudaFuncSetAttribute(logits_mma, cudaFuncAttributeMaxDynamicSharedMemorySize, 131072);

    gi_kernel<<<HW_, 384>>>(S, w_ih, b_ih);
    gru_kernel<<<1, 384>>>(w_hh, b_hh);
    mlp1_kernel<<<HW_ * NA_ / 64, 128>>>(A, S, W1, b1);
    mlp2_kernel<<<HW_ * NA_ / 64, 128>>>(W2, b2);
    logits_mma<<<dim3(2, HW_), 256, 131072>>>();
    softmax_kernel<<<HW_, 128>>>();
    ptrans_kernel<<<dim3(HW_, 8, 4), 256>>>();
    init_kernel<<<ROWS_, 256>>>(inputs);
    for (int it = 0; it < 15; ++it) {
        bellman_mma<<<dim3(4, 64), 256, BSMEM_>>>(it & 1);
    }
    int total = out_size < OUTT_ ? out_size : OUTT_;
    assemble_kernel<<<(total + 255) / 256, 256>>>(rnn_hxs, out, out_size);
}

// round 8
// speedup vs baseline: 4.5472x; 1.6126x over previous
#include <cuda_runtime.h>
#include <cuda_bf16.h>
#include <cuda_fp16.h>
#include <math.h>
#include <stdint.h>

// Problem constants
#define T_      8
#define N_      64
#define HW_     256
#define HID_    128
#define NA_     128
#define HX_     514
#define PASS_   258
#define ROWS_   512
#define OUT1_   263168
#define OUTT_   296064

typedef unsigned long long ull;

// ------------------------- scratch (device globals; no allocs) -------------
__device__ float g_gi[HW_ * 384];
__device__ __nv_bfloat16 g_Kh[HW_ * HID_];
__device__ __nv_bfloat16 g_Kl[HW_ * HID_];
__device__ float g_Y1[HW_ * NA_ * HID_];
__device__ __nv_bfloat16 g_Y2h[HW_ * NA_ * HID_];
__device__ __nv_bfloat16 g_Y2l[HW_ * NA_ * HID_];
__device__ float g_P[HW_ * HW_ * NA_];            // P[w][s][a] fp32
__device__ __half g_Pt[(size_t)HW_ * NA_ * HW_];  // [w][a][s] fp16
__device__ float g_R[ROWS_ * HW_];
__device__ float g_V[2][ROWS_ * HW_];             // fp32 ping-pong
__device__ __half g_Vq[2][ROWS_ * HW_];           // fp16 mirror

// ------------------------- ptx helpers -------------------------------------
__device__ __forceinline__ void fma2(ull& d, ull a, ull b) {
    asm("fma.rn.f32x2 %0, %1, %2, %0;" : "+l"(d) : "l"(a), "l"(b));
}
__device__ __forceinline__ float2 unpack2(ull u) {
    float2 f;
    asm("mov.b64 {%0, %1}, %2;" : "=f"(f.x), "=f"(f.y) : "l"(u));
    return f;
}
__device__ __forceinline__ ull pack2(float x, float y) {
    ull u;
    asm("mov.b64 %0, {%1, %2};" : "=l"(u) : "f"(x), "f"(y));
    return u;
}
__device__ __forceinline__ uint32_t smem_u32(const void* p) {
    uint32_t a;
    asm("{ .reg .u64 t; cvta.to.shared.u64 t, %1; cvt.u32.u64 %0, t; }" : "=r"(a) : "l"(p));
    return a;
}
__device__ __forceinline__ void cp_async16(uint32_t dst, const void* src) {
    asm volatile("cp.async.cg.shared.global [%0], [%1], 16;" ::"r"(dst), "l"(src) : "memory");
}
#define CP_COMMIT() asm volatile("cp.async.commit_group;" ::: "memory")

__device__ __forceinline__ void ldsm_x4(uint32_t* r, uint32_t addr) {
    asm volatile("ldmatrix.sync.aligned.m8n8.x4.shared.b16 {%0,%1,%2,%3}, [%4];"
                 : "=r"(r[0]), "=r"(r[1]), "=r"(r[2]), "=r"(r[3]) : "r"(addr));
}
__device__ __forceinline__ void mma16816(float* c, const uint32_t* a, const uint32_t* b) {
    asm volatile(
        "mma.sync.aligned.m16n8k16.row.col.f32.bf16.bf16.f32 "
        "{%0,%1,%2,%3}, {%4,%5,%6,%7}, {%8,%9}, {%0,%1,%2,%3};"
        : "+f"(c[0]), "+f"(c[1]), "+f"(c[2]), "+f"(c[3])
        : "r"(a[0]), "r"(a[1]), "r"(a[2]), "r"(a[3]), "r"(b[0]), "r"(b[1]));
}
__device__ __forceinline__ void mma16816h(float* c, const uint32_t* a, const uint32_t* b) {
    asm volatile(
        "mma.sync.aligned.m16n8k16.row.col.f32.f16.f16.f32 "
        "{%0,%1,%2,%3}, {%4,%5,%6,%7}, {%8,%9}, {%0,%1,%2,%3};"
        : "+f"(c[0]), "+f"(c[1]), "+f"(c[2]), "+f"(c[3])
        : "r"(a[0]), "r"(a[1]), "r"(a[2]), "r"(a[3]), "r"(b[0]), "r"(b[1]));
}

// swizzled 16KB tile: 128 rows x 128B, seg16 c in 0..7: addr = r*128 + ((c ^ (r&7))<<4)
#define TILE16 16384
__device__ __forceinline__ uint32_t sw_addr(uint32_t base, int r, int c16) {
    return base + r * 128 + (((uint32_t)(c16 ^ (r & 7))) << 4);
}
// bf16/f16 tile loader: 128 rows x 64 elems, elem stride given in elements
__device__ __forceinline__ void load_tile_sw(uint32_t dst, const __nv_bfloat16* src, int stride,
                                             int tid) {
#pragma unroll
    for (int i = 0; i < 4; ++i) {
        int lin = tid + i * 256;
        int r = lin >> 3, seg = lin & 7;
        cp_async16(sw_addr(dst, r, seg), src + (size_t)r * stride + seg * 8);
    }
}
// generic byte-based tile loader: 128 rows x 128B per row from rowBytes-strided src
__device__ __forceinline__ void load_tile_g(uint32_t dst, const void* src, int rowBytes, int tid) {
    const char* s = (const char*)src;
#pragma unroll
    for (int i = 0; i < 4; ++i) {
        int lin = tid + i * 256;
        int r = lin >> 3, seg = lin & 7;
        cp_async16(sw_addr(dst, r, seg), s + (size_t)r * rowBytes + seg * 16);
    }
}

// ------------------------- f32x2 tile core (mlp) ---------------------------
__device__ __forceinline__ void tile_fma(const float2 (&Xs2)[32][64], const float (&Bs)[32][128],
                                         ull (&acc)[8][4], int tx, int ty) {
    const ull* Xu = reinterpret_cast<const ull*>(&Xs2[0][0]);
#pragma unroll 8
    for (int k = 0; k < 32; ++k) {
        ulonglong2 a0 = *reinterpret_cast<const ulonglong2*>(Xu + k * 64 + ty * 8 + 0);
        ulonglong2 a1 = *reinterpret_cast<const ulonglong2*>(Xu + k * 64 + ty * 8 + 2);
        ulonglong2 a2 = *reinterpret_cast<const ulonglong2*>(Xu + k * 64 + ty * 8 + 4);
        ulonglong2 a3 = *reinterpret_cast<const ulonglong2*>(Xu + k * 64 + ty * 8 + 6);
        const ull* Bp = reinterpret_cast<const ull*>(&Bs[k][tx * 8]);
        ulonglong2 b0 = *reinterpret_cast<const ulonglong2*>(Bp + 0);
        ulonglong2 b1 = *reinterpret_cast<const ulonglong2*>(Bp + 2);
        ull av[8] = {a0.x, a0.y, a1.x, a1.y, a2.x, a2.y, a3.x, a3.y};
        ull bv[4] = {b0.x, b0.y, b1.x, b1.y};
#pragma unroll
        for (int r = 0; r < 8; ++r)
#pragma unroll
            for (int c = 0; c < 4; ++c) fma2(acc[r][c], av[r], bv[c]);
    }
}

// ------------------------- K1: gi ------------------------------------------
__global__ void gi_kernel(const float* __restrict__ S, const float* __restrict__ w_ih,
                          const float* __restrict__ b_ih) {
    __shared__ float Ss[HID_];
    int blk = blockIdx.x;
    int o = threadIdx.x;
    if (o < HID_) Ss[o] = S[blk * HID_ + o];
    __syncthreads();
    float acc = b_ih[o];
#pragma unroll 8
    for (int k = 0; k < HID_; k += 4) {
        float4 w = *reinterpret_cast<const float4*>(&w_ih[o * HID_ + k]);
        acc += Ss[k] * w.x + Ss[k + 1] * w.y + Ss[k + 2] * w.z + Ss[k + 3] * w.w;
    }
    g_gi[blk * 384 + o] = acc;
}

// ------------------------- K2: GRU (register weights, ILP4) ----------------
__global__ __launch_bounds__(384, 1) void gru_kernel(const float* __restrict__ w_hh,
                                                     const float* __restrict__ b_hh) {
    __shared__ __align__(16) float hs[HID_];
    __shared__ float ghs[384];
    int o = threadIdx.x;

    ull w2[64];
#pragma unroll
    for (int i = 0; i < 64; ++i) {
        float2 v = reinterpret_cast<const float2*>(w_hh)[o * 64 + i];
        w2[i] = pack2(v.x, v.y);
    }
    if (o < HID_) hs[o] = 0.0f;
    float bh = b_hh[o];
    __syncthreads();

    for (int t = 0; t < HW_; ++t) {
        ull z = pack2(0.0f, 0.0f);
        ull a0 = pack2(bh, 0.0f), a1 = z, a2 = z, a3 = z;
        const ull* h2 = reinterpret_cast<const ull*>(hs);
#pragma unroll
        for (int i = 0; i < 64; i += 4) {
            fma2(a0, h2[i], w2[i]);
            fma2(a1, h2[i + 1], w2[i + 1]);
            fma2(a2, h2[i + 2], w2[i + 2]);
            fma2(a3, h2[i + 3], w2[i + 3]);
        }
        float2 p0 = unpack2(a0), p1 = unpack2(a1), p2 = unpack2(a2), p3 = unpack2(a3);
        ghs[o] = (p0.x + p0.y) + (p1.x + p1.y) + ((p2.x + p2.y) + (p3.x + p3.y));
        __syncthreads();
        if (o < HID_) {
            float gir = g_gi[t * 384 + o];
            float giz = g_gi[t * 384 + 128 + o];
            float gin = g_gi[t * 384 + 256 + o];
            float r = 1.0f / (1.0f + expf(-(gir + ghs[o])));
            float zz = 1.0f / (1.0f + expf(-(giz + ghs[o + 128])));
            float n = tanhf(gin + r * ghs[o + 256]);
            float hn = (1.0f - zz) * n + zz * hs[o];
            hs[o] = hn;
            __nv_bfloat16 hi = __float2bfloat16(hn);
            g_Kh[t * HID_ + o] = hi;
            g_Kl[t * HID_ + o] = __float2bfloat16(hn - __bfloat162float(hi));
        }
        __syncthreads();
    }
}

// ------------------------- K3: MLP layer 1 ---------------------------------
__global__ __launch_bounds__(128) void mlp1_kernel(const float* __restrict__ A,
                                                   const float* __restrict__ S,
                                                   const float* __restrict__ W1,
                                                   const float* __restrict__ b1) {
    __shared__ float2 Xs2[32][64];
    __shared__ float Bs[32][128];
    int rb = blockIdx.x * 64;
    int w = rb >> 7, a0 = rb & 127;
    int tid = threadIdx.x, tx = tid & 15, ty = tid >> 4;
    ull acc[8][4] = {};
    for (int kc = 0; kc < HID_; kc += 32) {
        __syncthreads();
#pragma unroll
        for (int j = 0; j < 4; ++j) {
            int lin = tid + j * 128;
            int r = lin & 63, kq = lin >> 6;
            float4 av = *reinterpret_cast<const float4*>(&A[(a0 + r) * HID_ + kc + kq * 4]);
            float4 sv = *reinterpret_cast<const float4*>(&S[w * HID_ + kc + kq * 4]);
            float v0 = av.x + sv.x, v1 = av.y + sv.y, v2 = av.z + sv.z, v3 = av.w + sv.w;
            Xs2[kq * 4 + 0][r] = make_float2(v0, v0);
            Xs2[kq * 4 + 1][r] = make_float2(v1, v1);
            Xs2[kq * 4 + 2][r] = make_float2(v2, v2);
            Xs2[kq * 4 + 3][r] = make_float2(v3, v3);
        }
#pragma unroll
        for (int j = 0; j < 8; ++j) {
            float4 wv = *reinterpret_cast<const float4*>(&W1[tid * HID_ + kc + j * 4]);
            Bs[j * 4 + 0][tid] = wv.x;
            Bs[j * 4 + 1][tid] = wv.y;
            Bs[j * 4 + 2][tid] = wv.z;
            Bs[j * 4 + 3][tid] = wv.w;
        }
        __syncthreads();
        tile_fma(Xs2, Bs, acc, tx, ty);
    }
    float bb[8];
#pragma unroll
    for (int c = 0; c < 8; ++c) bb[c] = b1[tx * 8 + c];
#pragma unroll
    for (int i = 0; i < 8; ++i) {
        float o[8];
#pragma unroll
        for (int c = 0; c < 4; ++c) {
            float2 f = unpack2(acc[i][c]);
            o[2 * c] = fmaxf(f.x + bb[2 * c], 0.0f);
            o[2 * c + 1] = fmaxf(f.y + bb[2 * c + 1], 0.0f);
        }
        float* dst = &g_Y1[(rb + ty * 8 + i) * HID_ + tx * 8];
        *reinterpret_cast<float4*>(dst) = make_float4(o[0], o[1], o[2], o[3]);
        *reinterpret_cast<float4*>(dst + 4) = make_float4(o[4], o[5], o[6], o[7]);
    }
}

// ------------------------- K4: MLP layer 2 (writes bf16 split) -------------
__global__ __launch_bounds__(128) void mlp2_kernel(const float* __restrict__ W2,
                                                   const float* __restrict__ b2) {
    __shared__ float2 Xs2[32][64];
    __shared__ float Bs[32][128];
    int rb = blockIdx.x * 64;
    int tid = threadIdx.x, tx = tid & 15, ty = tid >> 4;
    ull acc[8][4] = {};
    for (int kc = 0; kc < HID_; kc += 32) {
        __syncthreads();
#pragma unroll
        for (int j = 0; j < 4; ++j) {
            int lin = tid + j * 128;
            int r = lin & 63, kq = lin >> 6;
            float4 v = *reinterpret_cast<const float4*>(&g_Y1[(rb + r) * HID_ + kc + kq * 4]);
            Xs2[kq * 4 + 0][r] = make_float2(v.x, v.x);
            Xs2[kq * 4 + 1][r] = make_float2(v.y, v.y);
            Xs2[kq * 4 + 2][r] = make_float2(v.z, v.z);
            Xs2[kq * 4 + 3][r] = make_float2(v.w, v.w);
        }
#pragma unroll
        for (int j = 0; j < 8; ++j) {
            float4 wv = *reinterpret_cast<const float4*>(&W2[tid * HID_ + kc + j * 4]);
            Bs[j * 4 + 0][tid] = wv.x;
            Bs[j * 4 + 1][tid] = wv.y;
            Bs[j * 4 + 2][tid] = wv.z;
            Bs[j * 4 + 3][tid] = wv.w;
        }
        __syncthreads();
        tile_fma(Xs2, Bs, acc, tx, ty);
    }
    float bb[8];
#pragma unroll
    for (int c = 0; c < 8; ++c) bb[c] = b2[tx * 8 + c];
#pragma unroll
    for (int i = 0; i < 8; ++i) {
        __nv_bfloat16 h8[8], l8[8];
#pragma unroll
        for (int c = 0; c < 4; ++c) {
            float2 f = unpack2(acc[i][c]);
            float o0 = fmaxf(f.x + bb[2 * c], 0.0f);
            float o1 = fmaxf(f.y + bb[2 * c + 1], 0.0f);
            h8[2 * c] = __float2bfloat16(o0);
            l8[2 * c] = __float2bfloat16(o0 - __bfloat162float(h8[2 * c]));
            h8[2 * c + 1] = __float2bfloat16(o1);
            l8[2 * c + 1] = __float2bfloat16(o1 - __bfloat162float(h8[2 * c + 1]));
        }
        size_t off = (size_t)(rb + ty * 8 + i) * HID_ + tx * 8;
        *reinterpret_cast<uint4*>(&g_Y2h[off]) = *reinterpret_cast<uint4*>(h8);
        *reinterpret_cast<uint4*>(&g_Y2l[off]) = *reinterpret_cast<uint4*>(l8);
    }
}

// ------------------------- K5: logits via mma.sync (bf16 3-prod) -----------
__global__ __launch_bounds__(256, 1) void logits_mma() {
    extern __shared__ char smem[];
    uint32_t sb = smem_u32(smem);
    int tid = threadIdx.x, wid = tid >> 5, lane = tid & 31;
    int s0 = blockIdx.x * 128;
    int w = blockIdx.y;
    int wr = wid >> 1, wc = wid & 1;

#pragma unroll
    for (int c = 0; c < 2; ++c) {
        load_tile_sw(sb + (0 * 2 + c) * TILE16, g_Kh + (size_t)s0 * 128 + c * 64, 128, tid);
        load_tile_sw(sb + (1 * 2 + c) * TILE16, g_Kl + (size_t)s0 * 128 + c * 64, 128, tid);
        load_tile_sw(sb + (2 * 2 + c) * TILE16, g_Y2h + (size_t)w * 128 * 128 + c * 64, 128, tid);
        load_tile_sw(sb + (3 * 2 + c) * TILE16, g_Y2l + (size_t)w * 128 * 128 + c * 64, 128, tid);
    }
    CP_COMMIT();
    asm volatile("cp.async.wait_group 0;" ::: "memory");
    __syncthreads();

    float acc[2][8][4];
#pragma unroll
    for (int mb = 0; mb < 2; ++mb)
#pragma unroll
        for (int nt = 0; nt < 8; ++nt)
#pragma unroll
            for (int q = 0; q < 4; ++q) acc[mb][nt][q] = 0.0f;

#pragma unroll
    for (int c = 0; c < 2; ++c) {
        uint32_t ahT = sb + c * TILE16, alT = sb + (2 + c) * TILE16;
        uint32_t bhT = sb + (4 + c) * TILE16, blT = sb + (6 + c) * TILE16;
#pragma unroll
        for (int kk = 0; kk < 4; ++kk) {
            uint32_t ah[2][4], al[2][4];
#pragma unroll
            for (int mb = 0; mb < 2; ++mb) {
                int r = wr * 32 + mb * 16 + (lane & 15);
                int c16 = (lane >> 4) + kk * 2;
                ldsm_x4(ah[mb], sw_addr(ahT, r, c16));
                ldsm_x4(al[mb], sw_addr(alT, r, c16));
            }
            uint32_t bh[8][2], bl[8][2];
#pragma unroll
            for (int np = 0; np < 4; ++np) {
                int n = wc * 64 + np * 16 + ((lane >> 4) << 3) + (lane & 7);
                int c16 = ((lane >> 3) & 1) + kk * 2;
                uint32_t r4[4];
                ldsm_x4(r4, sw_addr(bhT, n, c16));
                bh[np * 2][0] = r4[0]; bh[np * 2][1] = r4[1];
                bh[np * 2 + 1][0] = r4[2]; bh[np * 2 + 1][1] = r4[3];
                ldsm_x4(r4, sw_addr(blT, n, c16));
                bl[np * 2][0] = r4[0]; bl[np * 2][1] = r4[1];
                bl[np * 2 + 1][0] = r4[2]; bl[np * 2 + 1][1] = r4[3];
            }
#pragma unroll
            for (int mb = 0; mb < 2; ++mb)
#pragma unroll
                for (int nt = 0; nt < 8; ++nt) {
                    mma16816(acc[mb][nt], ah[mb], bh[nt]);
                    mma16816(acc[mb][nt], ah[mb], bl[nt]);
                    mma16816(acc[mb][nt], al[mb], bh[nt]);
                }
        }
    }
    int g = lane >> 2;
#pragma unroll
    for (int mb = 0; mb < 2; ++mb)
#pragma unroll
        for (int nt = 0; nt < 8; ++nt) {
            int row = wr * 32 + mb * 16 + g;
            int col = wc * 64 + nt * 8 + (lane & 3) * 2;
            float* d0 = &g_P[((size_t)w * HW_ + s0 + row) * NA_ + col];
            *reinterpret_cast<float2*>(d0) = make_float2(acc[mb][nt][0], acc[mb][nt][1]);
            float* d1 = &g_P[((size_t)w * HW_ + s0 + row + 8) * NA_ + col];
            *reinterpret_cast<float2*>(d1) = make_float2(acc[mb][nt][2], acc[mb][nt][3]);
        }
}

// ------------------------- K6: softmax over s ------------------------------
__global__ void softmax_kernel() {
    int w = blockIdx.x, a = threadIdx.x;
    float* base = g_P + (size_t)w * HW_ * NA_ + a;
    float m = -1e30f;
#pragma unroll 8
    for (int s = 0; s < HW_; ++s) m = fmaxf(m, base[s * NA_]);
    float sum = 0.0f;
#pragma unroll 8
    for (int s = 0; s < HW_; ++s) {
        float e = expf(base[s * NA_] - m);
        base[s * NA_] = e;
        sum += e;
    }
    float inv = 1.0f / sum;
#pragma unroll 8
    for (int s = 0; s < HW_; ++s) base[s * NA_] *= inv;
}

// ------------------------- K6b: P transpose + fp16 quant -------------------
// g_P[w][s][a] fp32 -> g_Pt[w][a][s] fp16
__global__ void ptrans_kernel() {
    __shared__ float tbuf[32][33];
    int w = blockIdx.x, s0 = blockIdx.y * 32, a0 = blockIdx.z * 32;
    int tx = threadIdx.x & 31, ty = threadIdx.x >> 5;  // 32x8
#pragma unroll
    for (int r = 0; r < 4; ++r) {
        int s = s0 + ty + r * 8;
        tbuf[ty + r * 8][tx] = g_P[((size_t)w * HW_ + s) * NA_ + a0 + tx];
    }
    __syncthreads();
#pragma unroll
    for (int r = 0; r < 4; ++r) {
        int a = a0 + ty + r * 8;
        float v = tbuf[tx][ty + r * 8];
        size_t idx = ((size_t)w * NA_ + a) * HW_ + s0 + tx;
        g_Pt[idx] = __float2half(v);
    }
}

// ------------------------- K7: rewards + V0 init ---------------------------
__global__ void init_kernel(const float* __restrict__ inputs) {
    int idx = blockIdx.x * blockDim.x + threadIdx.x;  // 512*256
    int row = idx >> 8, s = idx & 255;
    float v = inputs[row * 257 + s];
    g_R[idx] = v;
    g_V[0][idx] = v;
    g_Vq[0][idx] = __float2half(v);
}

// ------------------------- K8: Bellman via fp16 mma (1 product) ------------
// grid (4 mtiles, 64 w-groups), 256 thr. V fp16 K=256 resident in smem (64KB);
// P fp16 streamed: 16 iters (4 w x 4 chunks of 64 s), 2-stage double buffer.
// smem: V c0..c3 [0,64K) | P stages [64K,96K)
#define POFF_   65536
#define BSMEM_  98304

__global__ __launch_bounds__(256, 1) void bellman_h(int it) {
    extern __shared__ char smem[];
    __shared__ float red_s[8][32];
    uint32_t sb = smem_u32(smem);
    int tid = threadIdx.x, wid = tid >> 5, lane = tid & 31;
    int rb = blockIdx.x * 128;
    int wg = blockIdx.y * 4;
    int srcIdx = it & 1, dstIdx = srcIdx ^ 1;
    int wr = wid >> 1, wc = wid & 1;

    const char* vsrc = (const char*)(g_Vq[srcIdx] + (size_t)rb * 256);
    const char* pbase = (const char*)g_Pt;

    // prologue: V (4 tiles) + P(w0,c0) in group0; P(w0,c1) in group1
#pragma unroll
    for (int c = 0; c < 4; ++c) load_tile_g(sb + c * TILE16, vsrc + c * 128, 512, tid);
    load_tile_g(sb + POFF_, pbase + (size_t)wg * 65536, 512, tid);
    CP_COMMIT();
    load_tile_g(sb + POFF_ + TILE16, pbase + (size_t)wg * 65536 + 128, 512, tid);
    CP_COMMIT();

    float acc[2][8][4];
#pragma unroll
    for (int mb = 0; mb < 2; ++mb)
#pragma unroll
        for (int nt = 0; nt < 8; ++nt)
#pragma unroll
            for (int q = 0; q < 4; ++q) acc[mb][nt][q] = 0.0f;

    for (int i = 0; i < 16; ++i) {
        if (i < 15)
            asm volatile("cp.async.wait_group 1;" ::: "memory");
        else
            asm volatile("cp.async.wait_group 0;" ::: "memory");
        __syncthreads();

        int c = i & 3;
        uint32_t vT = sb + c * TILE16;
        uint32_t pT = sb + POFF_ + (i & 1) * TILE16;

#pragma unroll
        for (int kk = 0; kk < 4; ++kk) {
            uint32_t ah[2][4];
#pragma unroll
            for (int mb = 0; mb < 2; ++mb) {
                int r = wr * 32 + mb * 16 + (lane & 15);
                int c16 = (lane >> 4) + kk * 2;
                ldsm_x4(ah[mb], sw_addr(vT, r, c16));
            }
            uint32_t bh[8][2];
#pragma unroll
            for (int np = 0; np < 4; ++np) {
                int n = wc * 64 + np * 16 + ((lane >> 4) << 3) + (lane & 7);
                int c16 = ((lane >> 3) & 1) + kk * 2;
                uint32_t r4[4];
                ldsm_x4(r4, sw_addr(pT, n, c16));
                bh[np * 2][0] = r4[0]; bh[np * 2][1] = r4[1];
                bh[np * 2 + 1][0] = r4[2]; bh[np * 2 + 1][1] = r4[3];
            }
#pragma unroll
            for (int mb = 0; mb < 2; ++mb)
#pragma unroll
                for (int nt = 0; nt < 8; ++nt) mma16816h(acc[mb][nt], ah[mb], bh[nt]);
        }
        __syncthreads();

        if (i < 14) {
            int nx = i + 2;
            int wn = wg + (nx >> 2), cn = nx & 3;
            load_tile_g(sb + POFF_ + (i & 1) * TILE16,
                        pbase + (size_t)wn * 65536 + (size_t)cn * 128, 512, tid);
            CP_COMMIT();
        }

        if (c == 3) {  // w finished
            int w = wg + (i >> 2);
            int g = lane >> 2;
#pragma unroll
            for (int mb = 0; mb < 2; ++mb) {
                float mA = -1e30f, mB = -1e30f;
#pragma unroll
                for (int nt = 0; nt < 8; ++nt) {
                    mA = fmaxf(mA, fmaxf(acc[mb][nt][0], acc[mb][nt][1]));
                    mB = fmaxf(mB, fmaxf(acc[mb][nt][2], acc[mb][nt][3]));
                }
                mA = fmaxf(mA, __shfl_xor_sync(0xffffffffu, mA, 1));
                mA = fmaxf(mA, __shfl_xor_sync(0xffffffffu, mA, 2));
                mB = fmaxf(mB, __shfl_xor_sync(0xffffffffu, mB, 1));
                mB = fmaxf(mB, __shfl_xor_sync(0xffffffffu, mB, 2));
                if ((lane & 3) == 0) {
                    red_s[wid][mb * 16 + g] = mA;
                    red_s[wid][mb * 16 + 8 + g] = mB;
                }
            }
            __syncthreads();
            if (tid < 128) {
                int wrr = tid >> 5, rl = tid & 31;
                float m = fmaxf(red_s[wrr * 2][rl], red_s[wrr * 2 + 1][rl]);
                int row = rb + tid;
                float v = g_R[row * HW_ + w] + m;
                g_V[dstIdx][row * HW_ + w] = v;
                g_Vq[dstIdx][row * HW_ + w] = __float2half(v);
            }
#pragma unroll
            for (int mb = 0; mb < 2; ++mb)
#pragma unroll
                for (int nt = 0; nt < 8; ++nt)
#pragma unroll
                    for (int q = 0; q < 4; ++q) acc[mb][nt][q] = 0.0f;
        }
    }
}

// ------------------------- K9: output assembly -----------------------------
__global__ void assemble_kernel(const float* __restrict__ rnn_hxs, float* __restrict__ out,
                                int out_size) {
    int idx = blockIdx.x * blockDim.x + threadIdx.x;
    if (idx >= out_size || idx >= OUTT_) return;
    int row, c;
    if (idx < OUT1_) {
        row = idx / HX_;
        c = idx - row * HX_;
    } else {
        int k = idx - OUT1_;
        int r2 = k / HX_;
        c = k - r2 * HX_;
        row = 448 + r2;
    }
    float v = (c < PASS_) ? rnn_hxs[row * HX_ + c] : g_V[1][row * HW_ + (c - PASS_)];
    out[idx] = v;
}

// ------------------------- launcher ----------------------------------------
extern "C" void kernel_launch(void* const* d_in, const int* in_sizes, int n_in,
                              void* d_out, int out_size) {
    const float* inputs = (const float*)d_in[0];
    const float* rnn_hxs = (const float*)d_in[1];
    const float* S = (const float*)d_in[2];
    const float* A = (const float*)d_in[3];
    const float* w_ih = (const float*)d_in[4];
    const float* w_hh = (const float*)d_in[5];
    const float* b_ih = (const float*)d_in[6];
    const float* b_hh = (const float*)d_in[7];
    const float* W1 = (const float*)d_in[8];
    const float* b1 = (const float*)d_in[9];
    const float* W2 = (const float*)d_in[10];
    const float* b2 = (const float*)d_in[11];
    float* out = (float*)d_out;

    cudaFuncSetAttribute(bellman_h, cudaFuncAttributeMaxDynamicSharedMemorySize, BSMEM_);
    cudaFuncSetAttribute(logits_mma, cudaFuncAttributeMaxDynamicSharedMemorySize, 131072);

    gi_kernel<<<HW_, 384>>>(S, w_ih, b_ih);
    gru_kernel<<<1, 384>>>(w_hh, b_hh);
    mlp1_kernel<<<HW_ * NA_ / 64, 128>>>(A, S, W1, b1);
    mlp2_kernel<<<HW_ * NA_ / 64, 128>>>(W2, b2);
    logits_mma<<<dim3(2, HW_), 256, 131072>>>();
    softmax_kernel<<<HW_, 128>>>();
    ptrans_kernel<<<dim3(HW_, 8, 4), 256>>>();
    init_kernel<<<ROWS_, 256>>>(inputs);
    for (int it = 0; it < 15; ++it) {
        bellman_h<<<dim3(4, 64), 256, BSMEM_>>>(it);
    }
    int total = out_size < OUTT_ ? out_size : OUTT_;
    assemble_kernel<<<(total + 255) / 256, 256>>>(rnn_hxs, out, out_size);
}

// round 9
// speedup vs baseline: 4.8225x; 1.0605x over previous
#include <cuda_runtime.h>
#include <cuda_bf16.h>
#include <cuda_fp16.h>
#include <math.h>
#include <stdint.h>

// Problem constants
#define T_      8
#define N_      64
#define HW_     256
#define HID_    128
#define NA_     128
#define HX_     514
#define PASS_   258
#define ROWS_   512
#define OUT1_   263168
#define OUTT_   296064

typedef unsigned long long ull;

// ------------------------- scratch (device globals; no allocs) -------------
__device__ float g_gi[HW_ * 384];
__device__ __nv_bfloat16 g_Kh[HW_ * HID_];
__device__ __nv_bfloat16 g_Kl[HW_ * HID_];
__device__ __nv_bfloat16 g_Y1h[HW_ * NA_ * HID_];
__device__ __nv_bfloat16 g_Y1l[HW_ * NA_ * HID_];
__device__ __nv_bfloat16 g_Y2h[HW_ * NA_ * HID_];
__device__ __nv_bfloat16 g_Y2l[HW_ * NA_ * HID_];
__device__ __nv_bfloat16 g_W2h[HID_ * HID_];
__device__ __nv_bfloat16 g_W2l[HID_ * HID_];
__device__ float g_P[HW_ * HW_ * NA_];            // P[w][s][a] fp32
__device__ __half g_Pt[(size_t)HW_ * NA_ * HW_];  // [w][a][s] fp16
__device__ float g_R[ROWS_ * HW_];
__device__ float g_V[ROWS_ * HW_];                // fp32 values
__device__ __half g_Wq[ROWS_ * HW_];              // fp16 centered values
__device__ float g_mu[ROWS_];                     // per-row mean

// ------------------------- ptx helpers -------------------------------------
__device__ __forceinline__ void fma2(ull& d, ull a, ull b) {
    asm("fma.rn.f32x2 %0, %1, %2, %0;" : "+l"(d) : "l"(a), "l"(b));
}
__device__ __forceinline__ float2 unpack2(ull u) {
    float2 f;
    asm("mov.b64 {%0, %1}, %2;" : "=f"(f.x), "=f"(f.y) : "l"(u));
    return f;
}
__device__ __forceinline__ ull pack2(float x, float y) {
    ull u;
    asm("mov.b64 %0, {%1, %2};" : "=l"(u) : "f"(x), "f"(y));
    return u;
}
__device__ __forceinline__ uint32_t smem_u32(const void* p) {
    uint32_t a;
    asm("{ .reg .u64 t; cvta.to.shared.u64 t, %1; cvt.u32.u64 %0, t; }" : "=r"(a) : "l"(p));
    return a;
}
__device__ __forceinline__ void cp_async16(uint32_t dst, const void* src) {
    asm volatile("cp.async.cg.shared.global [%0], [%1], 16;" ::"r"(dst), "l"(src) : "memory");
}
#define CP_COMMIT() asm volatile("cp.async.commit_group;" ::: "memory")

__device__ __forceinline__ void ldsm_x4(uint32_t* r, uint32_t addr) {
    asm volatile("ldmatrix.sync.aligned.m8n8.x4.shared.b16 {%0,%1,%2,%3}, [%4];"
                 : "=r"(r[0]), "=r"(r[1]), "=r"(r[2]), "=r"(r[3]) : "r"(addr));
}
__device__ __forceinline__ void mma16816(float* c, const uint32_t* a, const uint32_t* b) {
    asm volatile(
        "mma.sync.aligned.m16n8k16.row.col.f32.bf16.bf16.f32 "
        "{%0,%1,%2,%3}, {%4,%5,%6,%7}, {%8,%9}, {%0,%1,%2,%3};"
        : "+f"(c[0]), "+f"(c[1]), "+f"(c[2]), "+f"(c[3])
        : "r"(a[0]), "r"(a[1]), "r"(a[2]), "r"(a[3]), "r"(b[0]), "r"(b[1]));
}
__device__ __forceinline__ void mma16816h(float* c, const uint32_t* a, const uint32_t* b) {
    asm volatile(
        "mma.sync.aligned.m16n8k16.row.col.f32.f16.f16.f32 "
        "{%0,%1,%2,%3}, {%4,%5,%6,%7}, {%8,%9}, {%0,%1,%2,%3};"
        : "+f"(c[0]), "+f"(c[1]), "+f"(c[2]), "+f"(c[3])
        : "r"(a[0]), "r"(a[1]), "r"(a[2]), "r"(a[3]), "r"(b[0]), "r"(b[1]));
}

// swizzled 16KB tile: 128 rows x 128B, seg16 c in 0..7: addr = r*128 + ((c ^ (r&7))<<4)
#define TILE16 16384
__device__ __forceinline__ uint32_t sw_addr(uint32_t base, int r, int c16) {
    return base + r * 128 + (((uint32_t)(c16 ^ (r & 7))) << 4);
}
// bf16 tile loader: 128 rows x 64 elems, stride in elements
__device__ __forceinline__ void load_tile_sw(uint32_t dst, const __nv_bfloat16* src, int stride,
                                             int tid) {
#pragma unroll
    for (int i = 0; i < 4; ++i) {
        int lin = tid + i * 256;
        int r = lin >> 3, seg = lin & 7;
        cp_async16(sw_addr(dst, r, seg), src + (size_t)r * stride + seg * 8);
    }
}
// generic byte-based tile loader: 128 rows x 128B per row from rowBytes-strided src
__device__ __forceinline__ void load_tile_g(uint32_t dst, const void* src, int rowBytes, int tid) {
    const char* s = (const char*)src;
#pragma unroll
    for (int i = 0; i < 4; ++i) {
        int lin = tid + i * 256;
        int r = lin >> 3, seg = lin & 7;
        cp_async16(sw_addr(dst, r, seg), s + (size_t)r * rowBytes + seg * 16);
    }
}

// ------------------------- f32x2 tile core (mlp1) --------------------------
__device__ __forceinline__ void tile_fma(const float2 (&Xs2)[32][64], const float (&Bs)[32][128],
                                         ull (&acc)[8][4], int tx, int ty) {
    const ull* Xu = reinterpret_cast<const ull*>(&Xs2[0][0]);
#pragma unroll 8
    for (int k = 0; k < 32; ++k) {
        ulonglong2 a0 = *reinterpret_cast<const ulonglong2*>(Xu + k * 64 + ty * 8 + 0);
        ulonglong2 a1 = *reinterpret_cast<const ulonglong2*>(Xu + k * 64 + ty * 8 + 2);
        ulonglong2 a2 = *reinterpret_cast<const ulonglong2*>(Xu + k * 64 + ty * 8 + 4);
        ulonglong2 a3 = *reinterpret_cast<const ulonglong2*>(Xu + k * 64 + ty * 8 + 6);
        const ull* Bp = reinterpret_cast<const ull*>(&Bs[k][tx * 8]);
        ulonglong2 b0 = *reinterpret_cast<const ulonglong2*>(Bp + 0);
        ulonglong2 b1 = *reinterpret_cast<const ulonglong2*>(Bp + 2);
        ull av[8] = {a0.x, a0.y, a1.x, a1.y, a2.x, a2.y, a3.x, a3.y};
        ull bv[4] = {b0.x, b0.y, b1.x, b1.y};
#pragma unroll
        for (int r = 0; r < 8; ++r)
#pragma unroll
            for (int c = 0; c < 4; ++c) fma2(acc[r][c], av[r], bv[c]);
    }
}

// ------------------------- K1: gi ------------------------------------------
__global__ void gi_kernel(const float* __restrict__ S, const float* __restrict__ w_ih,
                          const float* __restrict__ b_ih) {
    __shared__ float Ss[HID_];
    int blk = blockIdx.x;
    int o = threadIdx.x;
    if (o < HID_) Ss[o] = S[blk * HID_ + o];
    __syncthreads();
    float acc = b_ih[o];
#pragma unroll 8
    for (int k = 0; k < HID_; k += 4) {
        float4 w = *reinterpret_cast<const float4*>(&w_ih[o * HID_ + k]);
        acc += Ss[k] * w.x + Ss[k + 1] * w.y + Ss[k + 2] * w.z + Ss[k + 3] * w.w;
    }
    g_gi[blk * 384 + o] = acc;
}

// ------------------------- K2: GRU (register weights, ILP4) ----------------
__global__ __launch_bounds__(384, 1) void gru_kernel(const float* __restrict__ w_hh,
                                                     const float* __restrict__ b_hh) {
    __shared__ __align__(16) float hs[HID_];
    __shared__ float ghs[384];
    int o = threadIdx.x;

    ull w2[64];
#pragma unroll
    for (int i = 0; i < 64; ++i) {
        float2 v = reinterpret_cast<const float2*>(w_hh)[o * 64 + i];
        w2[i] = pack2(v.x, v.y);
    }
    if (o < HID_) hs[o] = 0.0f;
    float bh = b_hh[o];
    __syncthreads();

    for (int t = 0; t < HW_; ++t) {
        ull z = pack2(0.0f, 0.0f);
        ull a0 = pack2(bh, 0.0f), a1 = z, a2 = z, a3 = z;
        const ull* h2 = reinterpret_cast<const ull*>(hs);
#pragma unroll
        for (int i = 0; i < 64; i += 4) {
            fma2(a0, h2[i], w2[i]);
            fma2(a1, h2[i + 1], w2[i + 1]);
            fma2(a2, h2[i + 2], w2[i + 2]);
            fma2(a3, h2[i + 3], w2[i + 3]);
        }
        float2 p0 = unpack2(a0), p1 = unpack2(a1), p2 = unpack2(a2), p3 = unpack2(a3);
        ghs[o] = (p0.x + p0.y) + (p1.x + p1.y) + ((p2.x + p2.y) + (p3.x + p3.y));
        __syncthreads();
        if (o < HID_) {
            float gir = g_gi[t * 384 + o];
            float giz = g_gi[t * 384 + 128 + o];
            float gin = g_gi[t * 384 + 256 + o];
            float r = 1.0f / (1.0f + expf(-(gir + ghs[o])));
            float zz = 1.0f / (1.0f + expf(-(giz + ghs[o + 128])));
            float n = tanhf(gin + r * ghs[o + 256]);
            float hn = (1.0f - zz) * n + zz * hs[o];
            hs[o] = hn;
            __nv_bfloat16 hi = __float2bfloat16(hn);
            g_Kh[t * HID_ + o] = hi;
            g_Kl[t * HID_ + o] = __float2bfloat16(hn - __bfloat162float(hi));
        }
        __syncthreads();
    }
}

// ------------------------- K3: MLP layer 1 (writes bf16 split) -------------
__global__ __launch_bounds__(128) void mlp1_kernel(const float* __restrict__ A,
                                                   const float* __restrict__ S,
                                                   const float* __restrict__ W1,
                                                   const float* __restrict__ b1) {
    __shared__ float2 Xs2[32][64];
    __shared__ float Bs[32][128];
    int rb = blockIdx.x * 64;
    int w = rb >> 7, a0 = rb & 127;
    int tid = threadIdx.x, tx = tid & 15, ty = tid >> 4;
    ull acc[8][4] = {};
    for (int kc = 0; kc < HID_; kc += 32) {
        __syncthreads();
#pragma unroll
        for (int j = 0; j < 4; ++j) {
            int lin = tid + j * 128;
            int r = lin & 63, kq = lin >> 6;
            float4 av = *reinterpret_cast<const float4*>(&A[(a0 + r) * HID_ + kc + kq * 4]);
            float4 sv = *reinterpret_cast<const float4*>(&S[w * HID_ + kc + kq * 4]);
            float v0 = av.x + sv.x, v1 = av.y + sv.y, v2 = av.z + sv.z, v3 = av.w + sv.w;
            Xs2[kq * 4 + 0][r] = make_float2(v0, v0);
            Xs2[kq * 4 + 1][r] = make_float2(v1, v1);
            Xs2[kq * 4 + 2][r] = make_float2(v2, v2);
            Xs2[kq * 4 + 3][r] = make_float2(v3, v3);
        }
#pragma unroll
        for (int j = 0; j < 8; ++j) {
            float4 wv = *reinterpret_cast<const float4*>(&W1[tid * HID_ + kc + j * 4]);
            Bs[j * 4 + 0][tid] = wv.x;
            Bs[j * 4 + 1][tid] = wv.y;
            Bs[j * 4 + 2][tid] = wv.z;
            Bs[j * 4 + 3][tid] = wv.w;
        }
        __syncthreads();
        tile_fma(Xs2, Bs, acc, tx, ty);
    }
    float bb[8];
#pragma unroll
    for (int c = 0; c < 8; ++c) bb[c] = b1[tx * 8 + c];
#pragma unroll
    for (int i = 0; i < 8; ++i) {
        __nv_bfloat16 h8[8], l8[8];
#pragma unroll
        for (int c = 0; c < 4; ++c) {
            float2 f = unpack2(acc[i][c]);
            float o0 = fmaxf(f.x + bb[2 * c], 0.0f);
            float o1 = fmaxf(f.y + bb[2 * c + 1], 0.0f);
            h8[2 * c] = __float2bfloat16(o0);
            l8[2 * c] = __float2bfloat16(o0 - __bfloat162float(h8[2 * c]));
            h8[2 * c + 1] = __float2bfloat16(o1);
            l8[2 * c + 1] = __float2bfloat16(o1 - __bfloat162float(h8[2 * c + 1]));
        }
        size_t off = (size_t)(rb + ty * 8 + i) * HID_ + tx * 8;
        *reinterpret_cast<uint4*>(&g_Y1h[off]) = *reinterpret_cast<uint4*>(h8);
        *reinterpret_cast<uint4*>(&g_Y1l[off]) = *reinterpret_cast<uint4*>(l8);
    }
}

// ------------------------- K3b: split W2 -----------------------------------
__global__ void wsplit_kernel(const float* __restrict__ W2) {
    for (int i = threadIdx.x; i < HID_ * HID_; i += blockDim.x) {
        float v = W2[i];
        __nv_bfloat16 hi = __float2bfloat16(v);
        g_W2h[i] = hi;
        g_W2l[i] = __float2bfloat16(v - __bfloat162float(hi));
    }
}

// ------------------------- K4: MLP layer 2 via mma (bf16 3-prod) -----------
// grid 256 (row tiles of 128), 256 thr. Y2 = relu(Y1 @ W2^T + b2).
__global__ __launch_bounds__(256, 1) void mlp2_mma(const float* __restrict__ b2) {
    extern __shared__ char smem[];
    uint32_t sb = smem_u32(smem);
    int tid = threadIdx.x, wid = tid >> 5, lane = tid & 31;
    int rt = blockIdx.x;
    int wr = wid >> 1, wc = wid & 1;

#pragma unroll
    for (int c = 0; c < 2; ++c) {
        load_tile_sw(sb + (0 * 2 + c) * TILE16, g_Y1h + (size_t)rt * 16384 + c * 64, 128, tid);
        load_tile_sw(sb + (1 * 2 + c) * TILE16, g_Y1l + (size_t)rt * 16384 + c * 64, 128, tid);
        load_tile_sw(sb + (2 * 2 + c) * TILE16, g_W2h + c * 64, 128, tid);
        load_tile_sw(sb + (3 * 2 + c) * TILE16, g_W2l + c * 64, 128, tid);
    }
    CP_COMMIT();
    asm volatile("cp.async.wait_group 0;" ::: "memory");
    __syncthreads();

    float acc[2][8][4];
#pragma unroll
    for (int mb = 0; mb < 2; ++mb)
#pragma unroll
        for (int nt = 0; nt < 8; ++nt)
#pragma unroll
            for (int q = 0; q < 4; ++q) acc[mb][nt][q] = 0.0f;

#pragma unroll
    for (int c = 0; c < 2; ++c) {
        uint32_t ahT = sb + c * TILE16, alT = sb + (2 + c) * TILE16;
        uint32_t bhT = sb + (4 + c) * TILE16, blT = sb + (6 + c) * TILE16;
#pragma unroll
        for (int kk = 0; kk < 4; ++kk) {
            uint32_t ah[2][4], al[2][4];
#pragma unroll
            for (int mb = 0; mb < 2; ++mb) {
                int r = wr * 32 + mb * 16 + (lane & 15);
                int c16 = (lane >> 4) + kk * 2;
                ldsm_x4(ah[mb], sw_addr(ahT, r, c16));
                ldsm_x4(al[mb], sw_addr(alT, r, c16));
            }
            uint32_t bh[8][2], bl[8][2];
#pragma unroll
            for (int np = 0; np < 4; ++np) {
                int n = wc * 64 + np * 16 + ((lane >> 4) << 3) + (lane & 7);
                int c16 = ((lane >> 3) & 1) + kk * 2;
                uint32_t r4[4];
                ldsm_x4(r4, sw_addr(bhT, n, c16));
                bh[np * 2][0] = r4[0]; bh[np * 2][1] = r4[1];
                bh[np * 2 + 1][0] = r4[2]; bh[np * 2 + 1][1] = r4[3];
                ldsm_x4(r4, sw_addr(blT, n, c16));
                bl[np * 2][0] = r4[0]; bl[np * 2][1] = r4[1];
                bl[np * 2 + 1][0] = r4[2]; bl[np * 2 + 1][1] = r4[3];
            }
#pragma unroll
            for (int mb = 0; mb < 2; ++mb)
#pragma unroll
                for (int nt = 0; nt < 8; ++nt) {
                    mma16816(acc[mb][nt], ah[mb], bh[nt]);
                    mma16816(acc[mb][nt], ah[mb], bl[nt]);
                    mma16816(acc[mb][nt], al[mb], bh[nt]);
                }
        }
    }
    int g = lane >> 2;
#pragma unroll
    for (int mb = 0; mb < 2; ++mb)
#pragma unroll
        for (int nt = 0; nt < 8; ++nt) {
            int col = wc * 64 + nt * 8 + (lane & 3) * 2;
            float bb0 = b2[col], bb1 = b2[col + 1];
#pragma unroll
            for (int h = 0; h < 2; ++h) {
                int row = rt * 128 + wr * 32 + mb * 16 + g + h * 8;
                float o0 = fmaxf(acc[mb][nt][2 * h] + bb0, 0.0f);
                float o1 = fmaxf(acc[mb][nt][2 * h + 1] + bb1, 0.0f);
                __nv_bfloat16 h0 = __float2bfloat16(o0);
                __nv_bfloat16 h1 = __float2bfloat16(o1);
                __nv_bfloat162 hp, lp;
                hp.x = h0; hp.y = h1;
                lp.x = __float2bfloat16(o0 - __bfloat162float(h0));
                lp.y = __float2bfloat16(o1 - __bfloat162float(h1));
                *reinterpret_cast<__nv_bfloat162*>(&g_Y2h[(size_t)row * HID_ + col]) = hp;
                *reinterpret_cast<__nv_bfloat162*>(&g_Y2l[(size_t)row * HID_ + col]) = lp;
            }
        }
}

// ------------------------- K5: logits via mma.sync (bf16 3-prod) -----------
__global__ __launch_bounds__(256, 1) void logits_mma() {
    extern __shared__ char smem[];
    uint32_t sb = smem_u32(smem);
    int tid = threadIdx.x, wid = tid >> 5, lane = tid & 31;
    int s0 = blockIdx.x * 128;
    int w = blockIdx.y;
    int wr = wid >> 1, wc = wid & 1;

#pragma unroll
    for (int c = 0; c < 2; ++c) {
        load_tile_sw(sb + (0 * 2 + c) * TILE16, g_Kh + (size_t)s0 * 128 + c * 64, 128, tid);
        load_tile_sw(sb + (1 * 2 + c) * TILE16, g_Kl + (size_t)s0 * 128 + c * 64, 128, tid);
        load_tile_sw(sb + (2 * 2 + c) * TILE16, g_Y2h + (size_t)w * 128 * 128 + c * 64, 128, tid);
        load_tile_sw(sb + (3 * 2 + c) * TILE16, g_Y2l + (size_t)w * 128 * 128 + c * 64, 128, tid);
    }
    CP_COMMIT();
    asm volatile("cp.async.wait_group 0;" ::: "memory");
    __syncthreads();

    float acc[2][8][4];
#pragma unroll
    for (int mb = 0; mb < 2; ++mb)
#pragma unroll
        for (int nt = 0; nt < 8; ++nt)
#pragma unroll
            for (int q = 0; q < 4; ++q) acc[mb][nt][q] = 0.0f;

#pragma unroll
    for (int c = 0; c < 2; ++c) {
        uint32_t ahT = sb + c * TILE16, alT = sb + (2 + c) * TILE16;
        uint32_t bhT = sb + (4 + c) * TILE16, blT = sb + (6 + c) * TILE16;
#pragma unroll
        for (int kk = 0; kk < 4; ++kk) {
            uint32_t ah[2][4], al[2][4];
#pragma unroll
            for (int mb = 0; mb < 2; ++mb) {
                int r = wr * 32 + mb * 16 + (lane & 15);
                int c16 = (lane >> 4) + kk * 2;
                ldsm_x4(ah[mb], sw_addr(ahT, r, c16));
                ldsm_x4(al[mb], sw_addr(alT, r, c16));
            }
            uint32_t bh[8][2], bl[8][2];
#pragma unroll
            for (int np = 0; np < 4; ++np) {
                int n = wc * 64 + np * 16 + ((lane >> 4) << 3) + (lane & 7);
                int c16 = ((lane >> 3) & 1) + kk * 2;
                uint32_t r4[4];
                ldsm_x4(r4, sw_addr(bhT, n, c16));
                bh[np * 2][0] = r4[0]; bh[np * 2][1] = r4[1];
                bh[np * 2 + 1][0] = r4[2]; bh[np * 2 + 1][1] = r4[3];
                ldsm_x4(r4, sw_addr(blT, n, c16));
                bl[np * 2][0] = r4[0]; bl[np * 2][1] = r4[1];
                bl[np * 2 + 1][0] = r4[2]; bl[np * 2 + 1][1] = r4[3];
            }
#pragma unroll
            for (int mb = 0; mb < 2; ++mb)
#pragma unroll
                for (int nt = 0; nt < 8; ++nt) {
                    mma16816(acc[mb][nt], ah[mb], bh[nt]);
                    mma16816(acc[mb][nt], ah[mb], bl[nt]);
                    mma16816(acc[mb][nt], al[mb], bh[nt]);
                }
        }
    }
    int g = lane >> 2;
#pragma unroll
    for (int mb = 0; mb < 2; ++mb)
#pragma unroll
        for (int nt = 0; nt < 8; ++nt) {
            int row = wr * 32 + mb * 16 + g;
            int col = wc * 64 + nt * 8 + (lane & 3) * 2;
            float* d0 = &g_P[((size_t)w * HW_ + s0 + row) * NA_ + col];
            *reinterpret_cast<float2*>(d0) = make_float2(acc[mb][nt][0], acc[mb][nt][1]);
            float* d1 = &g_P[((size_t)w * HW_ + s0 + row + 8) * NA_ + col];
            *reinterpret_cast<float2*>(d1) = make_float2(acc[mb][nt][2], acc[mb][nt][3]);
        }
}

// ------------------------- K6: softmax over s ------------------------------
__global__ void softmax_kernel() {
    int w = blockIdx.x, a = threadIdx.x;
    float* base = g_P + (size_t)w * HW_ * NA_ + a;
    float m = -1e30f;
#pragma unroll 8
    for (int s = 0; s < HW_; ++s) m = fmaxf(m, base[s * NA_]);
    float sum = 0.0f;
#pragma unroll 8
    for (int s = 0; s < HW_; ++s) {
        float e = expf(base[s * NA_] - m);
        base[s * NA_] = e;
        sum += e;
    }
    float inv = 1.0f / sum;
#pragma unroll 8
    for (int s = 0; s < HW_; ++s) base[s * NA_] *= inv;
}

// ------------------------- K6b: P transpose + fp16 quant -------------------
__global__ void ptrans_kernel() {
    __shared__ float tbuf[32][33];
    int w = blockIdx.x, s0 = blockIdx.y * 32, a0 = blockIdx.z * 32;
    int tx = threadIdx.x & 31, ty = threadIdx.x >> 5;  // 32x8
#pragma unroll
    for (int r = 0; r < 4; ++r) {
        int s = s0 + ty + r * 8;
        tbuf[ty + r * 8][tx] = g_P[((size_t)w * HW_ + s) * NA_ + a0 + tx];
    }
    __syncthreads();
#pragma unroll
    for (int r = 0; r < 4; ++r) {
        int a = a0 + ty + r * 8;
        float v = tbuf[tx][ty + r * 8];
        size_t idx = ((size_t)w * NA_ + a) * HW_ + s0 + tx;
        g_Pt[idx] = __float2half(v);
    }
}

// ------------------------- K7: rewards + V0 init ---------------------------
__global__ void init_kernel(const float* __restrict__ inputs) {
    int idx = blockIdx.x * blockDim.x + threadIdx.x;  // 512*256
    int row = idx >> 8, s = idx & 255;
    float v = inputs[row * 257 + s];
    g_R[idx] = v;
    g_V[idx] = v;
}

// ------------------------- K7b: center + fp16 split of V -------------------
// one warp per row: mu = rowmean(V); Wq = fp16(V - mu)
__global__ __launch_bounds__(256) void vsplit_kernel() {
    int wid = threadIdx.x >> 5, lane = threadIdx.x & 31;
    int row = blockIdx.x * 8 + wid;
    const float* v = g_V + row * HW_;
    float4 a = *reinterpret_cast<const float4*>(v + lane * 8);
    float4 b = *reinterpret_cast<const float4*>(v + lane * 8 + 4);
    float s = ((a.x + a.y) + (a.z + a.w)) + ((b.x + b.y) + (b.z + b.w));
#pragma unroll
    for (int o = 16; o; o >>= 1) s += __shfl_xor_sync(0xffffffffu, s, o);
    float mu = s * (1.0f / 256.0f);
    __half h8[8];
    h8[0] = __float2half(a.x - mu);
    h8[1] = __float2half(a.y - mu);
    h8[2] = __float2half(a.z - mu);
    h8[3] = __float2half(a.w - mu);
    h8[4] = __float2half(b.x - mu);
    h8[5] = __float2half(b.y - mu);
    h8[6] = __float2half(b.z - mu);
    h8[7] = __float2half(b.w - mu);
    *reinterpret_cast<uint4*>(g_Wq + row * HW_ + lane * 8) = *reinterpret_cast<uint4*>(h8);
    if (lane == 0) g_mu[row] = mu;
}

// ------------------------- K8: Bellman via fp16 mma (1 product, centered) --
// grid (4 mtiles, 256 w), 256 thr. Wq (centered V) K=256 resident in smem;
// P fp16 streamed: 4 chunks of 64 s, 2-stage double buffer.
// smem: W c0..c3 [0,64K) | P stages [64K,96K)
#define POFF_   65536
#define BSMEM_  98304

__global__ __launch_bounds__(256, 1) void bellman_h() {
    extern __shared__ char smem[];
    __shared__ float red_s[8][32];
    uint32_t sb = smem_u32(smem);
    int tid = threadIdx.x, wid = tid >> 5, lane = tid & 31;
    int rb = blockIdx.x * 128;
    int w = blockIdx.y;
    int wr = wid >> 1, wc = wid & 1;

    const char* wsrc = (const char*)(g_Wq + (size_t)rb * 256);
    const char* pbase = (const char*)g_Pt + (size_t)w * 65536;

    // prologue: group0 = W tiles + P chunk0 ; group1 = P chunk1
#pragma unroll
    for (int c = 0; c < 4; ++c) load_tile_g(sb + c * TILE16, wsrc + c * 128, 512, tid);
    load_tile_g(sb + POFF_, pbase, 512, tid);
    CP_COMMIT();
    load_tile_g(sb + POFF_ + TILE16, pbase + 128, 512, tid);
    CP_COMMIT();

    float acc[2][8][4];
#pragma unroll
    for (int mb = 0; mb < 2; ++mb)
#pragma unroll
        for (int nt = 0; nt < 8; ++nt)
#pragma unroll
            for (int q = 0; q < 4; ++q) acc[mb][nt][q] = 0.0f;

#pragma unroll
    for (int i = 0; i < 4; ++i) {
        if (i < 3)
            asm volatile("cp.async.wait_group 1;" ::: "memory");
        else
            asm volatile("cp.async.wait_group 0;" ::: "memory");
        __syncthreads();

        uint32_t vT = sb + i * TILE16;
        uint32_t pT = sb + POFF_ + (i & 1) * TILE16;

#pragma unroll
        for (int kk = 0; kk < 4; ++kk) {
            uint32_t ah[2][4];
#pragma unroll
            for (int mb = 0; mb < 2; ++mb) {
                int r = wr * 32 + mb * 16 + (lane & 15);
                int c16 = (lane >> 4) + kk * 2;
                ldsm_x4(ah[mb], sw_addr(vT, r, c16));
            }
            uint32_t bh[8][2];
#pragma unroll
            for (int np = 0; np < 4; ++np) {
                int n = wc * 64 + np * 16 + ((lane >> 4) << 3) + (lane & 7);
                int c16 = ((lane >> 3) & 1) + kk * 2;
                uint32_t r4[4];
                ldsm_x4(r4, sw_addr(pT, n, c16));
                bh[np * 2][0] = r4[0]; bh[np * 2][1] = r4[1];
                bh[np * 2 + 1][0] = r4[2]; bh[np * 2 + 1][1] = r4[3];
            }
#pragma unroll
            for (int mb = 0; mb < 2; ++mb)
#pragma unroll
                for (int nt = 0; nt < 8; ++nt) mma16816h(acc[mb][nt], ah[mb], bh[nt]);
        }
        __syncthreads();

        if (i < 2) {
            load_tile_g(sb + POFF_ + (i & 1) * TILE16, pbase + (i + 2) * 128, 512, tid);
            CP_COMMIT();
        }
    }

    // epilogue: max over a, add R and mu back
    int g = lane >> 2;
#pragma unroll
    for (int mb = 0; mb < 2; ++mb) {
        float mA = -1e30f, mB = -1e30f;
#pragma unroll
        for (int nt = 0; nt < 8; ++nt) {
            mA = fmaxf(mA, fmaxf(acc[mb][nt][0], acc[mb][nt][1]));
            mB = fmaxf(mB, fmaxf(acc[mb][nt][2], acc[mb][nt][3]));
        }
        mA = fmaxf(mA, __shfl_xor_sync(0xffffffffu, mA, 1));
        mA = fmaxf(mA, __shfl_xor_sync(0xffffffffu, mA, 2));
        mB = fmaxf(mB, __shfl_xor_sync(0xffffffffu, mB, 1));
        mB = fmaxf(mB, __shfl_xor_sync(0xffffffffu, mB, 2));
        if ((lane & 3) == 0) {
            red_s[wid][mb * 16 + g] = mA;
            red_s[wid][mb * 16 + 8 + g] = mB;
        }
    }
    __syncthreads();
    if (tid < 128) {
        int wrr = tid >> 5, rl = tid & 31;
        float m = fmaxf(red_s[wrr * 2][rl], red_s[wrr * 2 + 1][rl]);
        int row = rb + tid;
        g_V[row * HW_ + w] = g_R[row * HW_ + w] + m + g_mu[row];
    }
}

// ------------------------- K9: output assembly -----------------------------
__global__ void assemble_kernel(const float* __restrict__ rnn_hxs, float* __restrict__ out,
                                int out_size) {
    int idx = blockIdx.x * blockDim.x + threadIdx.x;
    if (idx >= out_size || idx >= OUTT_) return;
    int row, c;
    if (idx < OUT1_) {
        row = idx / HX_;
        c = idx - row * HX_;
    } else {
        int k = idx - OUT1_;
        int r2 = k / HX_;
        c = k - r2 * HX_;
        row = 448 + r2;
    }
    float v = (c < PASS_) ? rnn_hxs[row * HX_ + c] : g_V[row * HW_ + (c - PASS_)];
    out[idx] = v;
}

// ------------------------- launcher ----------------------------------------
extern "C" void kernel_launch(void* const* d_in, const int* in_sizes, int n_in,
                              void* d_out, int out_size) {
    const float* inputs = (const float*)d_in[0];
    const float* rnn_hxs = (const float*)d_in[1];
    const float* S = (const float*)d_in[2];
    const float* A = (const float*)d_in[3];
    const float* w_ih = (const float*)d_in[4];
    const float* w_hh = (const float*)d_in[5];
    const float* b_ih = (const float*)d_in[6];
    const float* b_hh = (const float*)d_in[7];
    const float* W1 = (const float*)d_in[8];
    const float* b1 = (const float*)d_in[9];
    const float* W2 = (const float*)d_in[10];
    const float* b2 = (const float*)d_in[11];
    float* out = (float*)d_out;

    cudaFuncSetAttribute(bellman_h, cudaFuncAttributeMaxDynamicSharedMemorySize, BSMEM_);
    cudaFuncSetAttribute(logits_mma, cudaFuncAttributeMaxDynamicSharedMemorySize, 131072);
    cudaFuncSetAttribute(mlp2_mma, cudaFuncAttributeMaxDynamicSharedMemorySize, 131072);

    gi_kernel<<<HW_, 384>>>(S, w_ih, b_ih);
    gru_kernel<<<1, 384>>>(w_hh, b_hh);
    wsplit_kernel<<<1, 256>>>(W2);
    mlp1_kernel<<<HW_ * NA_ / 64, 128>>>(A, S, W1, b1);
    mlp2_mma<<<256, 256, 131072>>>(b2);
    logits_mma<<<dim3(2, HW_), 256, 131072>>>();
    softmax_kernel<<<HW_, 128>>>();
    ptrans_kernel<<<dim3(HW_, 8, 4), 256>>>();
    init_kernel<<<ROWS_, 256>>>(inputs);
    vsplit_kernel<<<ROWS_ / 8, 256>>>();
    for (int it = 0; it < 15; ++it) {
        bellman_h<<<dim3(4, HW_), 256, BSMEM_>>>();
        if (it < 14) vsplit_kernel<<<ROWS_ / 8, 256>>>();
    }
    int total = out_size < OUTT_ ? out_size : OUTT_;
    assemble_kernel<<<(total + 255) / 256, 256>>>(rnn_hxs, out, out_size);
}

// round 10
// speedup vs baseline: 4.9962x; 1.0360x over previous
#include <cuda_runtime.h>
#include <cuda_bf16.h>
#include <cuda_fp16.h>
#include <math.h>
#include <stdint.h>

// Problem constants
#define T_      8
#define N_      64
#define HW_     256
#define HID_    128
#define NA_     128
#define HX_     514
#define PASS_   258
#define ROWS_   512
#define OUT1_   263168
#define OUTT_   296064

typedef unsigned long long ull;

// ------------------------- scratch (device globals; no allocs) -------------
__device__ float g_gi[HW_ * 384];
__device__ __nv_bfloat16 g_Kh[HW_ * HID_];
__device__ __nv_bfloat16 g_Kl[HW_ * HID_];
__device__ __nv_bfloat16 g_Y1h[HW_ * NA_ * HID_];
__device__ __nv_bfloat16 g_Y1l[HW_ * NA_ * HID_];
__device__ __nv_bfloat16 g_Y2h[HW_ * NA_ * HID_];
__device__ __nv_bfloat16 g_Y2l[HW_ * NA_ * HID_];
__device__ __nv_bfloat16 g_W2h[HID_ * HID_];
__device__ __nv_bfloat16 g_W2l[HID_ * HID_];
__device__ float g_P[(size_t)HW_ * NA_ * HW_];    // L then P, layout [w][a][s] fp32
__device__ __half g_Pt[(size_t)HW_ * NA_ * HW_];  // [w][a][s] fp16
__device__ float g_R[ROWS_ * HW_];
__device__ float g_V[ROWS_ * HW_];                // fp32 values
__device__ __half g_Wq[ROWS_ * HW_];              // fp16 centered values
__device__ float g_mu[ROWS_];                     // per-row mean

// ------------------------- ptx helpers -------------------------------------
__device__ __forceinline__ void fma2(ull& d, ull a, ull b) {
    asm("fma.rn.f32x2 %0, %1, %2, %0;" : "+l"(d) : "l"(a), "l"(b));
}
__device__ __forceinline__ float2 unpack2(ull u) {
    float2 f;
    asm("mov.b64 {%0, %1}, %2;" : "=f"(f.x), "=f"(f.y) : "l"(u));
    return f;
}
__device__ __forceinline__ ull pack2(float x, float y) {
    ull u;
    asm("mov.b64 %0, {%1, %2};" : "=l"(u) : "f"(x), "f"(y));
    return u;
}
__device__ __forceinline__ uint32_t smem_u32(const void* p) {
    uint32_t a;
    asm("{ .reg .u64 t; cvta.to.shared.u64 t, %1; cvt.u32.u64 %0, t; }" : "=r"(a) : "l"(p));
    return a;
}
__device__ __forceinline__ void cp_async16(uint32_t dst, const void* src) {
    asm volatile("cp.async.cg.shared.global [%0], [%1], 16;" ::"r"(dst), "l"(src) : "memory");
}
#define CP_COMMIT() asm volatile("cp.async.commit_group;" ::: "memory")

__device__ __forceinline__ void ldsm_x4(uint32_t* r, uint32_t addr) {
    asm volatile("ldmatrix.sync.aligned.m8n8.x4.shared.b16 {%0,%1,%2,%3}, [%4];"
                 : "=r"(r[0]), "=r"(r[1]), "=r"(r[2]), "=r"(r[3]) : "r"(addr));
}
__device__ __forceinline__ void mma16816(float* c, const uint32_t* a, const uint32_t* b) {
    asm volatile(
        "mma.sync.aligned.m16n8k16.row.col.f32.bf16.bf16.f32 "
        "{%0,%1,%2,%3}, {%4,%5,%6,%7}, {%8,%9}, {%0,%1,%2,%3};"
        : "+f"(c[0]), "+f"(c[1]), "+f"(c[2]), "+f"(c[3])
        : "r"(a[0]), "r"(a[1]), "r"(a[2]), "r"(a[3]), "r"(b[0]), "r"(b[1]));
}
__device__ __forceinline__ void mma16816h(float* c, const uint32_t* a, const uint32_t* b) {
    asm volatile(
        "mma.sync.aligned.m16n8k16.row.col.f32.f16.f16.f32 "
        "{%0,%1,%2,%3}, {%4,%5,%6,%7}, {%8,%9}, {%0,%1,%2,%3};"
        : "+f"(c[0]), "+f"(c[1]), "+f"(c[2]), "+f"(c[3])
        : "r"(a[0]), "r"(a[1]), "r"(a[2]), "r"(a[3]), "r"(b[0]), "r"(b[1]));
}

// swizzled 16KB tile: 128 rows x 128B, seg16 c in 0..7: addr = r*128 + ((c ^ (r&7))<<4)
#define TILE16 16384
__device__ __forceinline__ uint32_t sw_addr(uint32_t base, int r, int c16) {
    return base + r * 128 + (((uint32_t)(c16 ^ (r & 7))) << 4);
}
// bf16 tile loader: 128 rows x 64 elems, stride in elements
__device__ __forceinline__ void load_tile_sw(uint32_t dst, const __nv_bfloat16* src, int stride,
                                             int tid) {
#pragma unroll
    for (int i = 0; i < 4; ++i) {
        int lin = tid + i * 256;
        int r = lin >> 3, seg = lin & 7;
        cp_async16(sw_addr(dst, r, seg), src + (size_t)r * stride + seg * 8);
    }
}
// generic byte-based tile loader: 128 rows x 128B per row from rowBytes-strided src
__device__ __forceinline__ void load_tile_g(uint32_t dst, const void* src, int rowBytes, int tid) {
    const char* s = (const char*)src;
#pragma unroll
    for (int i = 0; i < 4; ++i) {
        int lin = tid + i * 256;
        int r = lin >> 3, seg = lin & 7;
        cp_async16(sw_addr(dst, r, seg), s + (size_t)r * rowBytes + seg * 16);
    }
}

// ------------------------- f32x2 tile core (mlp1) --------------------------
__device__ __forceinline__ void tile_fma(const float2 (&Xs2)[32][64], const float (&Bs)[32][128],
                                         ull (&acc)[8][4], int tx, int ty) {
    const ull* Xu = reinterpret_cast<const ull*>(&Xs2[0][0]);
#pragma unroll 8
    for (int k = 0; k < 32; ++k) {
        ulonglong2 a0 = *reinterpret_cast<const ulonglong2*>(Xu + k * 64 + ty * 8 + 0);
        ulonglong2 a1 = *reinterpret_cast<const ulonglong2*>(Xu + k * 64 + ty * 8 + 2);
        ulonglong2 a2 = *reinterpret_cast<const ulonglong2*>(Xu + k * 64 + ty * 8 + 4);
        ulonglong2 a3 = *reinterpret_cast<const ulonglong2*>(Xu + k * 64 + ty * 8 + 6);
        const ull* Bp = reinterpret_cast<const ull*>(&Bs[k][tx * 8]);
        ulonglong2 b0 = *reinterpret_cast<const ulonglong2*>(Bp + 0);
        ulonglong2 b1 = *reinterpret_cast<const ulonglong2*>(Bp + 2);
        ull av[8] = {a0.x, a0.y, a1.x, a1.y, a2.x, a2.y, a3.x, a3.y};
        ull bv[4] = {b0.x, b0.y, b1.x, b1.y};
#pragma unroll
        for (int r = 0; r < 8; ++r)
#pragma unroll
            for (int c = 0; c < 4; ++c) fma2(acc[r][c], av[r], bv[c]);
    }
}

// ------------------------- K1: gi ------------------------------------------
__global__ void gi_kernel(const float* __restrict__ S, const float* __restrict__ w_ih,
                          const float* __restrict__ b_ih) {
    __shared__ float Ss[HID_];
    int blk = blockIdx.x;
    int o = threadIdx.x;
    if (o < HID_) Ss[o] = S[blk * HID_ + o];
    __syncthreads();
    float acc = b_ih[o];
#pragma unroll 8
    for (int k = 0; k < HID_; k += 4) {
        float4 w = *reinterpret_cast<const float4*>(&w_ih[o * HID_ + k]);
        acc += Ss[k] * w.x + Ss[k + 1] * w.y + Ss[k + 2] * w.z + Ss[k + 3] * w.w;
    }
    g_gi[blk * 384 + o] = acc;
}

// ------------------------- K2: GRU (register weights, ILP4) ----------------
__global__ __launch_bounds__(384, 1) void gru_kernel(const float* __restrict__ w_hh,
                                                     const float* __restrict__ b_hh) {
    __shared__ __align__(16) float hs[HID_];
    __shared__ float ghs[384];
    int o = threadIdx.x;

    ull w2[64];
#pragma unroll
    for (int i = 0; i < 64; ++i) {
        float2 v = reinterpret_cast<const float2*>(w_hh)[o * 64 + i];
        w2[i] = pack2(v.x, v.y);
    }
    if (o < HID_) hs[o] = 0.0f;
    float bh = b_hh[o];
    __syncthreads();

    for (int t = 0; t < HW_; ++t) {
        ull z = pack2(0.0f, 0.0f);
        ull a0 = pack2(bh, 0.0f), a1 = z, a2 = z, a3 = z;
        const ull* h2 = reinterpret_cast<const ull*>(hs);
#pragma unroll
        for (int i = 0; i < 64; i += 4) {
            fma2(a0, h2[i], w2[i]);
            fma2(a1, h2[i + 1], w2[i + 1]);
            fma2(a2, h2[i + 2], w2[i + 2]);
            fma2(a3, h2[i + 3], w2[i + 3]);
        }
        float2 p0 = unpack2(a0), p1 = unpack2(a1), p2 = unpack2(a2), p3 = unpack2(a3);
        ghs[o] = (p0.x + p0.y) + (p1.x + p1.y) + ((p2.x + p2.y) + (p3.x + p3.y));
        __syncthreads();
        if (o < HID_) {
            float gir = g_gi[t * 384 + o];
            float giz = g_gi[t * 384 + 128 + o];
            float gin = g_gi[t * 384 + 256 + o];
            float r = 1.0f / (1.0f + expf(-(gir + ghs[o])));
            float zz = 1.0f / (1.0f + expf(-(giz + ghs[o + 128])));
            float n = tanhf(gin + r * ghs[o + 256]);
            float hn = (1.0f - zz) * n + zz * hs[o];
            hs[o] = hn;
            __nv_bfloat16 hi = __float2bfloat16(hn);
            g_Kh[t * HID_ + o] = hi;
            g_Kl[t * HID_ + o] = __float2bfloat16(hn - __bfloat162float(hi));
        }
        __syncthreads();
    }
}

// ------------------------- K3: MLP layer 1 (writes bf16 split) -------------
__global__ __launch_bounds__(128) void mlp1_kernel(const float* __restrict__ A,
                                                   const float* __restrict__ S,
                                                   const float* __restrict__ W1,
                                                   const float* __restrict__ b1) {
    __shared__ float2 Xs2[32][64];
    __shared__ float Bs[32][128];
    int rb = blockIdx.x * 64;
    int w = rb >> 7, a0 = rb & 127;
    int tid = threadIdx.x, tx = tid & 15, ty = tid >> 4;
    ull acc[8][4] = {};
    for (int kc = 0; kc < HID_; kc += 32) {
        __syncthreads();
#pragma unroll
        for (int j = 0; j < 4; ++j) {
            int lin = tid + j * 128;
            int r = lin & 63, kq = lin >> 6;
            float4 av = *reinterpret_cast<const float4*>(&A[(a0 + r) * HID_ + kc + kq * 4]);
            float4 sv = *reinterpret_cast<const float4*>(&S[w * HID_ + kc + kq * 4]);
            float v0 = av.x + sv.x, v1 = av.y + sv.y, v2 = av.z + sv.z, v3 = av.w + sv.w;
            Xs2[kq * 4 + 0][r] = make_float2(v0, v0);
            Xs2[kq * 4 + 1][r] = make_float2(v1, v1);
            Xs2[kq * 4 + 2][r] = make_float2(v2, v2);
            Xs2[kq * 4 + 3][r] = make_float2(v3, v3);
        }
#pragma unroll
        for (int j = 0; j < 8; ++j) {
            float4 wv = *reinterpret_cast<const float4*>(&W1[tid * HID_ + kc + j * 4]);
            Bs[j * 4 + 0][tid] = wv.x;
            Bs[j * 4 + 1][tid] = wv.y;
            Bs[j * 4 + 2][tid] = wv.z;
            Bs[j * 4 + 3][tid] = wv.w;
        }
        __syncthreads();
        tile_fma(Xs2, Bs, acc, tx, ty);
    }
    float bb[8];
#pragma unroll
    for (int c = 0; c < 8; ++c) bb[c] = b1[tx * 8 + c];
#pragma unroll
    for (int i = 0; i < 8; ++i) {
        __nv_bfloat16 h8[8], l8[8];
#pragma unroll
        for (int c = 0; c < 4; ++c) {
            float2 f = unpack2(acc[i][c]);
            float o0 = fmaxf(f.x + bb[2 * c], 0.0f);
            float o1 = fmaxf(f.y + bb[2 * c + 1], 0.0f);
            h8[2 * c] = __float2bfloat16(o0);
            l8[2 * c] = __float2bfloat16(o0 - __bfloat162float(h8[2 * c]));
            h8[2 * c + 1] = __float2bfloat16(o1);
            l8[2 * c + 1] = __float2bfloat16(o1 - __bfloat162float(h8[2 * c + 1]));
        }
        size_t off = (size_t)(rb + ty * 8 + i) * HID_ + tx * 8;
        *reinterpret_cast<uint4*>(&g_Y1h[off]) = *reinterpret_cast<uint4*>(h8);
        *reinterpret_cast<uint4*>(&g_Y1l[off]) = *reinterpret_cast<uint4*>(l8);
    }
}

// ------------------------- K3b: split W2 -----------------------------------
__global__ void wsplit_kernel(const float* __restrict__ W2) {
    for (int i = threadIdx.x; i < HID_ * HID_; i += blockDim.x) {
        float v = W2[i];
        __nv_bfloat16 hi = __float2bfloat16(v);
        g_W2h[i] = hi;
        g_W2l[i] = __float2bfloat16(v - __bfloat162float(hi));
    }
}

// ------------------------- K4: MLP layer 2 via mma (bf16 3-prod) -----------
__global__ __launch_bounds__(256, 1) void mlp2_mma(const float* __restrict__ b2) {
    extern __shared__ char smem[];
    uint32_t sb = smem_u32(smem);
    int tid = threadIdx.x, wid = tid >> 5, lane = tid & 31;
    int rt = blockIdx.x;
    int wr = wid >> 1, wc = wid & 1;

#pragma unroll
    for (int c = 0; c < 2; ++c) {
        load_tile_sw(sb + (0 * 2 + c) * TILE16, g_Y1h + (size_t)rt * 16384 + c * 64, 128, tid);
        load_tile_sw(sb + (1 * 2 + c) * TILE16, g_Y1l + (size_t)rt * 16384 + c * 64, 128, tid);
        load_tile_sw(sb + (2 * 2 + c) * TILE16, g_W2h + c * 64, 128, tid);
        load_tile_sw(sb + (3 * 2 + c) * TILE16, g_W2l + c * 64, 128, tid);
    }
    CP_COMMIT();
    asm volatile("cp.async.wait_group 0;" ::: "memory");
    __syncthreads();

    float acc[2][8][4];
#pragma unroll
    for (int mb = 0; mb < 2; ++mb)
#pragma unroll
        for (int nt = 0; nt < 8; ++nt)
#pragma unroll
            for (int q = 0; q < 4; ++q) acc[mb][nt][q] = 0.0f;

#pragma unroll
    for (int c = 0; c < 2; ++c) {
        uint32_t ahT = sb + c * TILE16, alT = sb + (2 + c) * TILE16;
        uint32_t bhT = sb + (4 + c) * TILE16, blT = sb + (6 + c) * TILE16;
#pragma unroll
        for (int kk = 0; kk < 4; ++kk) {
            uint32_t ah[2][4], al[2][4];
#pragma unroll
            for (int mb = 0; mb < 2; ++mb) {
                int r = wr * 32 + mb * 16 + (lane & 15);
                int c16 = (lane >> 4) + kk * 2;
                ldsm_x4(ah[mb], sw_addr(ahT, r, c16));
                ldsm_x4(al[mb], sw_addr(alT, r, c16));
            }
            uint32_t bh[8][2], bl[8][2];
#pragma unroll
            for (int np = 0; np < 4; ++np) {
                int n = wc * 64 + np * 16 + ((lane >> 4) << 3) + (lane & 7);
                int c16 = ((lane >> 3) & 1) + kk * 2;
                uint32_t r4[4];
                ldsm_x4(r4, sw_addr(bhT, n, c16));
                bh[np * 2][0] = r4[0]; bh[np * 2][1] = r4[1];
                bh[np * 2 + 1][0] = r4[2]; bh[np * 2 + 1][1] = r4[3];
                ldsm_x4(r4, sw_addr(blT, n, c16));
                bl[np * 2][0] = r4[0]; bl[np * 2][1] = r4[1];
                bl[np * 2 + 1][0] = r4[2]; bl[np * 2 + 1][1] = r4[3];
            }
#pragma unroll
            for (int mb = 0; mb < 2; ++mb)
#pragma unroll
                for (int nt = 0; nt < 8; ++nt) {
                    mma16816(acc[mb][nt], ah[mb], bh[nt]);
                    mma16816(acc[mb][nt], ah[mb], bl[nt]);
                    mma16816(acc[mb][nt], al[mb], bh[nt]);
                }
        }
    }
    int g = lane >> 2;
#pragma unroll
    for (int mb = 0; mb < 2; ++mb)
#pragma unroll
        for (int nt = 0; nt < 8; ++nt) {
            int col = wc * 64 + nt * 8 + (lane & 3) * 2;
            float bb0 = b2[col], bb1 = b2[col + 1];
#pragma unroll
            for (int h = 0; h < 2; ++h) {
                int row = rt * 128 + wr * 32 + mb * 16 + g + h * 8;
                float o0 = fmaxf(acc[mb][nt][2 * h] + bb0, 0.0f);
                float o1 = fmaxf(acc[mb][nt][2 * h + 1] + bb1, 0.0f);
                __nv_bfloat16 h0 = __float2bfloat16(o0);
                __nv_bfloat16 h1 = __float2bfloat16(o1);
                __nv_bfloat162 hp, lp;
                hp.x = h0; hp.y = h1;
                lp.x = __float2bfloat16(o0 - __bfloat162float(h0));
                lp.y = __float2bfloat16(o1 - __bfloat162float(h1));
                *reinterpret_cast<__nv_bfloat162*>(&g_Y2h[(size_t)row * HID_ + col]) = hp;
                *reinterpret_cast<__nv_bfloat162*>(&g_Y2l[(size_t)row * HID_ + col]) = lp;
            }
        }
}

// ------------------------- K5: logits via mma.sync, writes [w][a][s] -------
__global__ __launch_bounds__(256, 1) void logits_mma() {
    extern __shared__ char smem[];
    uint32_t sb = smem_u32(smem);
    int tid = threadIdx.x, wid = tid >> 5, lane = tid & 31;
    int s0 = blockIdx.x * 128;
    int w = blockIdx.y;
    int wr = wid >> 1, wc = wid & 1;

#pragma unroll
    for (int c = 0; c < 2; ++c) {
        load_tile_sw(sb + (0 * 2 + c) * TILE16, g_Kh + (size_t)s0 * 128 + c * 64, 128, tid);
        load_tile_sw(sb + (1 * 2 + c) * TILE16, g_Kl + (size_t)s0 * 128 + c * 64, 128, tid);
        load_tile_sw(sb + (2 * 2 + c) * TILE16, g_Y2h + (size_t)w * 128 * 128 + c * 64, 128, tid);
        load_tile_sw(sb + (3 * 2 + c) * TILE16, g_Y2l + (size_t)w * 128 * 128 + c * 64, 128, tid);
    }
    CP_COMMIT();
    asm volatile("cp.async.wait_group 0;" ::: "memory");
    __syncthreads();

    float acc[2][8][4];
#pragma unroll
    for (int mb = 0; mb < 2; ++mb)
#pragma unroll
        for (int nt = 0; nt < 8; ++nt)
#pragma unroll
            for (int q = 0; q < 4; ++q) acc[mb][nt][q] = 0.0f;

#pragma unroll
    for (int c = 0; c < 2; ++c) {
        uint32_t ahT = sb + c * TILE16, alT = sb + (2 + c) * TILE16;
        uint32_t bhT = sb + (4 + c) * TILE16, blT = sb + (6 + c) * TILE16;
#pragma unroll
        for (int kk = 0; kk < 4; ++kk) {
            uint32_t ah[2][4], al[2][4];
#pragma unroll
            for (int mb = 0; mb < 2; ++mb) {
                int r = wr * 32 + mb * 16 + (lane & 15);
                int c16 = (lane >> 4) + kk * 2;
                ldsm_x4(ah[mb], sw_addr(ahT, r, c16));
                ldsm_x4(al[mb], sw_addr(alT, r, c16));
            }
            uint32_t bh[8][2], bl[8][2];
#pragma unroll
            for (int np = 0; np < 4; ++np) {
                int n = wc * 64 + np * 16 + ((lane >> 4) << 3) + (lane & 7);
                int c16 = ((lane >> 3) & 1) + kk * 2;
                uint32_t r4[4];
                ldsm_x4(r4, sw_addr(bhT, n, c16));
                bh[np * 2][0] = r4[0]; bh[np * 2][1] = r4[1];
                bh[np * 2 + 1][0] = r4[2]; bh[np * 2 + 1][1] = r4[3];
                ldsm_x4(r4, sw_addr(blT, n, c16));
                bl[np * 2][0] = r4[0]; bl[np * 2][1] = r4[1];
                bl[np * 2 + 1][0] = r4[2]; bl[np * 2 + 1][1] = r4[3];
            }
#pragma unroll
            for (int mb = 0; mb < 2; ++mb)
#pragma unroll
                for (int nt = 0; nt < 8; ++nt) {
                    mma16816(acc[mb][nt], ah[mb], bh[nt]);
                    mma16816(acc[mb][nt], ah[mb], bl[nt]);
                    mma16816(acc[mb][nt], al[mb], bh[nt]);
                }
        }
    }
    // transposed store: L[w][a=col][s=s0+row]
    int g = lane >> 2;
#pragma unroll
    for (int mb = 0; mb < 2; ++mb)
#pragma unroll
        for (int nt = 0; nt < 8; ++nt) {
            int row = wr * 32 + mb * 16 + g;
            int col = wc * 64 + nt * 8 + (lane & 3) * 2;
            size_t b0 = ((size_t)w * NA_ + col) * HW_ + s0 + row;
            g_P[b0] = acc[mb][nt][0];
            g_P[b0 + HW_] = acc[mb][nt][1];
            g_P[b0 + 8] = acc[mb][nt][2];
            g_P[b0 + HW_ + 8] = acc[mb][nt][3];
        }
}

// ------------------------- K6: row softmax over s + fp16 out ---------------
// one warp per (w,a) row of 256 contiguous floats; writes g_Pt fp16
__global__ __launch_bounds__(256) void softmax_rows() {
    int wid = threadIdx.x >> 5, lane = threadIdx.x & 31;
    size_t row = (size_t)blockIdx.x * 8 + wid;  // 0..32767
    const float* base = g_P + row * HW_;
    float4 a = *reinterpret_cast<const float4*>(base + lane * 8);
    float4 b = *reinterpret_cast<const float4*>(base + lane * 8 + 4);
    float m = fmaxf(fmaxf(fmaxf(a.x, a.y), fmaxf(a.z, a.w)),
                    fmaxf(fmaxf(b.x, b.y), fmaxf(b.z, b.w)));
#pragma unroll
    for (int o = 16; o; o >>= 1) m = fmaxf(m, __shfl_xor_sync(0xffffffffu, m, o));
    float e[8];
    e[0] = expf(a.x - m); e[1] = expf(a.y - m); e[2] = expf(a.z - m); e[3] = expf(a.w - m);
    e[4] = expf(b.x - m); e[5] = expf(b.y - m); e[6] = expf(b.z - m); e[7] = expf(b.w - m);
    float s = ((e[0] + e[1]) + (e[2] + e[3])) + ((e[4] + e[5]) + (e[6] + e[7]));
#pragma unroll
    for (int o = 16; o; o >>= 1) s += __shfl_xor_sync(0xffffffffu, s, o);
    float inv = 1.0f / s;
    __half h8[8];
#pragma unroll
    for (int i = 0; i < 8; ++i) h8[i] = __float2half(e[i] * inv);
    *reinterpret_cast<uint4*>(g_Pt + row * HW_ + lane * 8) = *reinterpret_cast<uint4*>(h8);
}

// ------------------------- K7: rewards + V0 init + center/split ------------
// one block per row: mean over 256 w, write R/V/Wq/mu
__global__ __launch_bounds__(256) void init_kernel(const float* __restrict__ inputs) {
    __shared__ float part[8];
    int row = blockIdx.x, t = threadIdx.x;
    int wid = t >> 5, lane = t & 31;
    float v = inputs[row * 257 + t];
    g_R[row * HW_ + t] = v;
    g_V[row * HW_ + t] = v;
    float s = v;
#pragma unroll
    for (int o = 16; o; o >>= 1) s += __shfl_xor_sync(0xffffffffu, s, o);
    if (lane == 0) part[wid] = s;
    __syncthreads();
    float tot = ((part[0] + part[1]) + (part[2] + part[3])) +
                ((part[4] + part[5]) + (part[6] + part[7]));
    float mu = tot * (1.0f / 256.0f);
    g_Wq[row * HW_ + t] = __float2half(v - mu);
    if (t == 0) g_mu[row] = mu;
}

// ------------------------- K7b: center + fp16 split of V -------------------
__global__ __launch_bounds__(256) void vsplit_kernel() {
    int wid = threadIdx.x >> 5, lane = threadIdx.x & 31;
    int row = blockIdx.x * 8 + wid;
    const float* v = g_V + row * HW_;
    float4 a = *reinterpret_cast<const float4*>(v + lane * 8);
    float4 b = *reinterpret_cast<const float4*>(v + lane * 8 + 4);
    float s = ((a.x + a.y) + (a.z + a.w)) + ((b.x + b.y) + (b.z + b.w));
#pragma unroll
    for (int o = 16; o; o >>= 1) s += __shfl_xor_sync(0xffffffffu, s, o);
    float mu = s * (1.0f / 256.0f);
    __half h8[8];
    h8[0] = __float2half(a.x - mu);
    h8[1] = __float2half(a.y - mu);
    h8[2] = __float2half(a.z - mu);
    h8[3] = __float2half(a.w - mu);
    h8[4] = __float2half(b.x - mu);
    h8[5] = __float2half(b.y - mu);
    h8[6] = __float2half(b.z - mu);
    h8[7] = __float2half(b.w - mu);
    *reinterpret_cast<uint4*>(g_Wq + row * HW_ + lane * 8) = *reinterpret_cast<uint4*>(h8);
    if (lane == 0) g_mu[row] = mu;
}

// ------------------------- K8: Bellman via fp16 mma (1 product, centered) --
#define POFF_   65536
#define BSMEM_  98304

__global__ __launch_bounds__(256, 1) void bellman_h() {
    extern __shared__ char smem[];
    __shared__ float red_s[8][32];
    uint32_t sb = smem_u32(smem);
    int tid = threadIdx.x, wid = tid >> 5, lane = tid & 31;
    int rb = blockIdx.x * 128;
    int w = blockIdx.y;
    int wr = wid >> 1, wc = wid & 1;

    const char* wsrc = (const char*)(g_Wq + (size_t)rb * 256);
    const char* pbase = (const char*)g_Pt + (size_t)w * 65536;

#pragma unroll
    for (int c = 0; c < 4; ++c) load_tile_g(sb + c * TILE16, wsrc + c * 128, 512, tid);
    load_tile_g(sb + POFF_, pbase, 512, tid);
    CP_COMMIT();
    load_tile_g(sb + POFF_ + TILE16, pbase + 128, 512, tid);
    CP_COMMIT();

    float acc[2][8][4];
#pragma unroll
    for (int mb = 0; mb < 2; ++mb)
#pragma unroll
        for (int nt = 0; nt < 8; ++nt)
#pragma unroll
            for (int q = 0; q < 4; ++q) acc[mb][nt][q] = 0.0f;

#pragma unroll
    for (int i = 0; i < 4; ++i) {
        if (i < 3)
            asm volatile("cp.async.wait_group 1;" ::: "memory");
        else
            asm volatile("cp.async.wait_group 0;" ::: "memory");
        __syncthreads();

        uint32_t vT = sb + i * TILE16;
        uint32_t pT = sb + POFF_ + (i & 1) * TILE16;

#pragma unroll
        for (int kk = 0; kk < 4; ++kk) {
            uint32_t ah[2][4];
#pragma unroll
            for (int mb = 0; mb < 2; ++mb) {
                int r = wr * 32 + mb * 16 + (lane & 15);
                int c16 = (lane >> 4) + kk * 2;
                ldsm_x4(ah[mb], sw_addr(vT, r, c16));
            }
            uint32_t bh[8][2];
#pragma unroll
            for (int np = 0; np < 4; ++np) {
                int n = wc * 64 + np * 16 + ((lane >> 4) << 3) + (lane & 7);
                int c16 = ((lane >> 3) & 1) + kk * 2;
                uint32_t r4[4];
                ldsm_x4(r4, sw_addr(pT, n, c16));
                bh[np * 2][0] = r4[0]; bh[np * 2][1] = r4[1];
                bh[np * 2 + 1][0] = r4[2]; bh[np * 2 + 1][1] = r4[3];
            }
#pragma unroll
            for (int mb = 0; mb < 2; ++mb)
#pragma unroll
                for (int nt = 0; nt < 8; ++nt) mma16816h(acc[mb][nt], ah[mb], bh[nt]);
        }
        __syncthreads();

        if (i < 2) {
            load_tile_g(sb + POFF_ + (i & 1) * TILE16, pbase + (i + 2) * 128, 512, tid);
            CP_COMMIT();
        }
    }

    int g = lane >> 2;
#pragma unroll
    for (int mb = 0; mb < 2; ++mb) {
        float mA = -1e30f, mB = -1e30f;
#pragma unroll
        for (int nt = 0; nt < 8; ++nt) {
            mA = fmaxf(mA, fmaxf(acc[mb][nt][0], acc[mb][nt][1]));
            mB = fmaxf(mB, fmaxf(acc[mb][nt][2], acc[mb][nt][3]));
        }
        mA = fmaxf(mA, __shfl_xor_sync(0xffffffffu, mA, 1));
        mA = fmaxf(mA, __shfl_xor_sync(0xffffffffu, mA, 2));
        mB = fmaxf(mB, __shfl_xor_sync(0xffffffffu, mB, 1));
        mB = fmaxf(mB, __shfl_xor_sync(0xffffffffu, mB, 2));
        if ((lane & 3) == 0) {
            red_s[wid][mb * 16 + g] = mA;
            red_s[wid][mb * 16 + 8 + g] = mB;
        }
    }
    __syncthreads();
    if (tid < 128) {
        int wrr = tid >> 5, rl = tid & 31;
        float m = fmaxf(red_s[wrr * 2][rl], red_s[wrr * 2 + 1][rl]);
        int row = rb + tid;
        g_V[row * HW_ + w] = g_R[row * HW_ + w] + m + g_mu[row];
    }
}

// ------------------------- K9: output assembly -----------------------------
__global__ void assemble_kernel(const float* __restrict__ rnn_hxs, float* __restrict__ out,
                                int out_size) {
    int idx = blockIdx.x * blockDim.x + threadIdx.x;
    if (idx >= out_size || idx >= OUTT_) return;
    int row, c;
    if (idx < OUT1_) {
        row = idx / HX_;
        c = idx - row * HX_;
    } else {
        int k = idx - OUT1_;
        int r2 = k / HX_;
        c = k - r2 * HX_;
        row = 448 + r2;
    }
    float v = (c < PASS_) ? rnn_hxs[row * HX_ + c] : g_V[row * HW_ + (c - PASS_)];
    out[idx] = v;
}

// ------------------------- launcher ----------------------------------------
extern "C" void kernel_launch(void* const* d_in, const int* in_sizes, int n_in,
                              void* d_out, int out_size) {
    const float* inputs = (const float*)d_in[0];
    const float* rnn_hxs = (const float*)d_in[1];
    const float* S = (const float*)d_in[2];
    const float* A = (const float*)d_in[3];
    const float* w_ih = (const float*)d_in[4];
    const float* w_hh = (const float*)d_in[5];
    const float* b_ih = (const float*)d_in[6];
    const float* b_hh = (const float*)d_in[7];
    const float* W1 = (const float*)d_in[8];
    const float* b1 = (const float*)d_in[9];
    const float* W2 = (const float*)d_in[10];
    const float* b2 = (const float*)d_in[11];
    float* out = (float*)d_out;

    cudaFuncSetAttribute(bellman_h, cudaFuncAttributeMaxDynamicSharedMemorySize, BSMEM_);
    cudaFuncSetAttribute(logits_mma, cudaFuncAttributeMaxDynamicSharedMemorySize, 131072);
    cudaFuncSetAttribute(mlp2_mma, cudaFuncAttributeMaxDynamicSharedMemorySize, 131072);

    gi_kernel<<<HW_, 384>>>(S, w_ih, b_ih);
    gru_kernel<<<1, 384>>>(w_hh, b_hh);
    wsplit_kernel<<<1, 256>>>(W2);
    mlp1_kernel<<<HW_ * NA_ / 64, 128>>>(A, S, W1, b1);
    mlp2_mma<<<256, 256, 131072>>>(b2);
    logits_mma<<<dim3(2, HW_), 256, 131072>>>();
    softmax_rows<<<HW_ * NA_ / 8, 256>>>();
    init_kernel<<<ROWS_, 256>>>(inputs);
    for (int it = 0; it < 15; ++it) {
        bellman_h<<<dim3(4, HW_), 256, BSMEM_>>>();
        if (it < 14) vsplit_kernel<<<ROWS_ / 8, 256>>>();
    }
    int total = out_size < OUTT_ ? out_size : OUTT_;
    assemble_kernel<<<(total + 255) / 256, 256>>>(rnn_hxs, out, out_size);
}